// round 10
// baseline (speedup 1.0000x reference)
#include <cuda_runtime.h>
#include <cuda_bf16.h>
#include <cstdint>

// ---------------- problem constants ----------------
#define NTOK 1024
#define DIN  1024
#define NCLS 267735
// regions: [0,20000) head, [20000,40000), [40000,200000), [200000,267735)

// ---------------- GEMM tile config ----------------
#define TM 128
#define TN 256
#define KC 32               // k per pipeline stage
#define NKC 32              // DIN / KC
#define GT 256              // 8 warps: 2 M-warps x 4 N-warps, warp tile 64x64

// N-tile counts per region (classes / TN, ceil)
#define NT0 79
#define NT1 79
#define NT2 625
#define NT3 265
#define NT_TOTAL (NT0 + NT1 + NT2 + NT3)   // 1048

// smem layout: A bf16 2 x 8KB (paired-row SW128), B f32 2 x 32KB (SW128)
#define SA(buf) ((buf) * 8192)
#define SB(buf) (16384 + (buf) * 32768)
#define SBIAS 81920                          // 256 f32
#define SLIST 82944                          // 128 int
#define SROW  83456                          // 128 f32
#define SMEM_TOTAL 83968

#define SW(o) ((o) ^ (((o) >> 3) & 0x70))    // SW128 swizzle on byte offsets

// ---------------- device scratch (static; no allocation) ----------------
__device__ __nv_bfloat16 g_hbf[NTOK * DIN];  // bf16 hidden
__device__ float g_S[4][NTOK];
__device__ int   g_list[4][NTOK];
__device__ int   g_count[4];
__device__ float g_tlogit[NTOK];
__device__ float g_clogit[NTOK][3];
__device__ int   g_cid[NTOK];

// ---------------- small helpers ----------------
__device__ __forceinline__ uint32_t smem_u32(const void* p) {
    uint32_t a;
    asm("{ .reg .u64 t; cvta.to.shared.u64 t, %1; cvt.u32.u64 %0, t; }" : "=r"(a) : "l"(p));
    return a;
}
__device__ __forceinline__ uint32_t pack_bf16(float lo, float hi) {
    __nv_bfloat162 h = __floats2bfloat162_rn(lo, hi);   // .x = lo (low half)
    return *reinterpret_cast<uint32_t*>(&h);
}
__device__ __forceinline__ void cp_async16(uint32_t saddr, const void* gaddr) {
    asm volatile("cp.async.cg.shared.global [%0], [%1], 16;" :: "r"(saddr), "l"(gaddr));
}
#define CP_COMMIT() asm volatile("cp.async.commit_group;" ::: "memory")
#define CP_WAIT(n)  asm volatile("cp.async.wait_group %0;" :: "n"(n) : "memory")
__device__ __forceinline__ void lds_frag4(uint32_t r[4], uint32_t addr) {
    asm volatile("ldmatrix.sync.aligned.m8n8.x4.shared.b16 {%0,%1,%2,%3}, [%4];"
        : "=r"(r[0]), "=r"(r[1]), "=r"(r[2]), "=r"(r[3]) : "r"(addr));
}
__device__ __forceinline__ float2 lds_f2(uint32_t addr) {
    float2 v;
    asm volatile("ld.shared.v2.f32 {%0,%1}, [%2];" : "=f"(v.x), "=f"(v.y) : "r"(addr));
    return v;
}
__device__ __forceinline__ void mma16816(float d[4], const uint32_t a[4],
                                         uint32_t b0, uint32_t b1) {
    asm volatile("mma.sync.aligned.m16n8k16.row.col.f32.bf16.bf16.f32 "
        "{%0,%1,%2,%3}, {%4,%5,%6,%7}, {%8,%9}, {%0,%1,%2,%3};"
        : "+f"(d[0]), "+f"(d[1]), "+f"(d[2]), "+f"(d[3])
        : "r"(a[0]), "r"(a[1]), "r"(a[2]), "r"(a[3]), "r"(b0), "r"(b1));
}

// ---------------- kernel 0: reset scratch ----------------
__global__ void zero_kernel() {
    int t = threadIdx.x;
    for (int i = t; i < 4 * NTOK; i += blockDim.x) (&g_S[0][0])[i] = 0.0f;
    for (int i = t; i < NTOK; i += blockDim.x) g_list[0][i] = i;
    if (t == 0) g_count[0] = NTOK;
    if (t >= 1 && t < 4) g_count[t] = 0;
}

// ---------------- f32 -> bf16 streaming convert (hidden only; 8 elems/thread) ----------------
__global__ void convert_kernel(const float* __restrict__ src,
                               __nv_bfloat16* __restrict__ dst, size_t n8) {
    size_t i = (size_t)blockIdx.x * blockDim.x + threadIdx.x;
    if (i >= n8) return;
    const float4* p = reinterpret_cast<const float4*>(src) + i * 2;
    float4 a = p[0], b = p[1];
    uint4 o;
    o.x = pack_bf16(a.x, a.y); o.y = pack_bf16(a.z, a.w);
    o.z = pack_bf16(b.x, b.y); o.w = pack_bf16(b.z, b.w);
    reinterpret_cast<uint4*>(dst)[i] = o;
}

// ---------------- kernel 1: per-token prep (exact f32 dots + compaction) ----------------
__global__ void prep_kernel(const float* __restrict__ hidden,
                            const int* __restrict__ target,   // int32 (JAX x64 disabled)
                            const float* __restrict__ weight,
                            const float* __restrict__ bias,
                            const float* __restrict__ cw,
                            const float* __restrict__ cb) {
    int gw = (int)((blockIdx.x * blockDim.x + threadIdx.x) >> 5);
    int lane = threadIdx.x & 31;
    if (gw >= NTOK) return;
    const int t = target[gw];
    const float4* h4  = reinterpret_cast<const float4*>(hidden + (size_t)gw * DIN);
    const float4* w4  = reinterpret_cast<const float4*>(weight + (size_t)t * DIN);
    const float4* c40 = reinterpret_cast<const float4*>(cw);
    const float4* c41 = reinterpret_cast<const float4*>(cw + DIN);
    const float4* c42 = reinterpret_cast<const float4*>(cw + 2 * DIN);
    float at = 0.f, a0 = 0.f, a1 = 0.f, a2 = 0.f;
#pragma unroll
    for (int j = 0; j < 8; j++) {
        int i = lane + 32 * j;
        float4 h = h4[i];
        float4 w = w4[i];
        at += h.x * w.x + h.y * w.y + h.z * w.z + h.w * w.w;
        float4 q = c40[i]; a0 += h.x * q.x + h.y * q.y + h.z * q.z + h.w * q.w;
        q = c41[i];        a1 += h.x * q.x + h.y * q.y + h.z * q.z + h.w * q.w;
        q = c42[i];        a2 += h.x * q.x + h.y * q.y + h.z * q.z + h.w * q.w;
    }
#pragma unroll
    for (int o = 16; o > 0; o >>= 1) {
        at += __shfl_xor_sync(0xffffffffu, at, o);
        a0 += __shfl_xor_sync(0xffffffffu, a0, o);
        a1 += __shfl_xor_sync(0xffffffffu, a1, o);
        a2 += __shfl_xor_sync(0xffffffffu, a2, o);
    }
    if (lane == 0) {
        g_tlogit[gw] = at + bias[t];
        g_clogit[gw][0] = a0 + cb[0];
        g_clogit[gw][1] = a1 + cb[1];
        g_clogit[gw][2] = a2 + cb[2];
        int r = (t < 20000) ? 0 : (t < 40000) ? 1 : (t < 200000) ? 2 : 3;
        g_cid[gw] = r;
        if (r > 0) {
            int idx = atomicAdd(&g_count[r], 1);
            g_list[r][idx] = gw;
        }
    }
}

// ---------------- kernel 2: merged HMMA GEMM (A bf16 smem, B f32 smem + reg cvt) ----------------
__global__ __launch_bounds__(GT, 1)
void gemm_sumexp(const float* __restrict__ weight,
                 const float* __restrict__ bias) {
    extern __shared__ char smem[];
    const int tid = threadIdx.x;

    int nt = blockIdx.y;
    int region, lo, width;
    if (nt < NT0)                  { region = 0; lo = 0;      width = 20000;  }
    else if (nt < NT0 + NT1)       { region = 1; lo = 20000;  width = 20000;  nt -= NT0; }
    else if (nt < NT0 + NT1 + NT2) { region = 2; lo = 40000;  width = 160000; nt -= NT0 + NT1; }
    else                           { region = 3; lo = 200000; width = 67735;  nt -= NT0 + NT1 + NT2; }

    const int count = g_count[region];
    const int row0 = blockIdx.x * TM;        // M fastest -> weight-tile sharers concurrent
    if (row0 >= count) return;
    const int col0 = nt * TN;
    const uint32_t sb = smem_u32(smem);

    if (tid < TM) {
        int rr = row0 + tid;
        if (rr > count - 1) rr = count - 1;
        reinterpret_cast<int*>(smem + SLIST)[tid] = g_list[region][rr];
        reinterpret_cast<float*>(smem + SROW)[tid] = 0.0f;
    }
    {   // bias tile: 256 entries, one per thread
        int cls = col0 + tid;
        reinterpret_cast<float*>(smem + SBIAS)[tid] =
            (cls < width) ? bias[lo + cls] : __int_as_float(0xff800000);  // -inf
    }
    __syncthreads();

    const int* listp = reinterpret_cast<const int*>(smem + SLIST);
    const int lane = tid & 31, wid = tid >> 5;

    // ---- A (bf16) cp.async mapping: 2 ops/thread/chunk; paired-row SW128 layout
    // o = (r>>1)*128 + (r&1)*64 + kbyte  -> conflict-free ldmatrix at KC=32
    uint32_t aoff[2], soffA[2];
    {
        int posA = lane & 3;                 // 16B unit within 64B row-chunk
#pragma unroll
        for (int j = 0; j < 2; j++) {
            int r = wid * 16 + j * 8 + (lane >> 2);     // 0..127
            aoff[j] = (uint32_t)listp[r] * DIN + posA * 8;   // bf16 elems
            uint32_t o = (uint32_t)((r >> 1) * 128 + (r & 1) * 64 + posA * 16);
            soffA[j] = SW(o);
        }
    }
    // ---- B (f32) cp.async mapping: 8 ops/thread/chunk; rows 128B, SW128
    uint32_t boff[8], soffB[8];
    {
        int posB = lane & 7;                 // 16B unit within 128B row
#pragma unroll
        for (int j = 0; j < 8; j++) {
            int r = wid * 32 + j * 4 + (lane >> 3);     // 0..255
            int cls = col0 + r;
            boff[j] = (uint32_t)(lo + ((cls < width) ? cls : width - 1)) * DIN + posB * 4;
            soffB[j] = SW((uint32_t)(r * 128 + posB * 16));
        }
    }

    const int wm = wid & 1, wn = wid >> 1;   // 2 M-warps x 4 N-warps

    // B fragment addressing: row n0 -> byte n0*128; swizzle XOR X = (n0&7)<<4
    // applies to the FULL in-row offset c (compute c first, then XOR).
    uint32_t brow[4], bX[4];
    const uint32_t c8 = (uint32_t)((lane & 3) * 8);   // this thread's k-pair byte offset
#pragma unroll
    for (int np = 0; np < 4; np++) {
        int n0 = wn * 64 + np * 16 + (lane >> 2);
        brow[np] = (uint32_t)(n0 * 128);
        bX[np] = (uint32_t)((n0 & 7) << 4);
    }

    float acc[4][8][4];
#pragma unroll
    for (int mi = 0; mi < 4; mi++)
#pragma unroll
        for (int nj = 0; nj < 8; nj++)
#pragma unroll
            for (int e = 0; e < 4; e++) acc[mi][nj][e] = 0.0f;

    // ---- async load of chunk 0 ----
#pragma unroll
    for (int j = 0; j < 2; j++) cp_async16(sb + SA(0) + soffA[j], g_hbf + aoff[j]);
#pragma unroll
    for (int j = 0; j < 8; j++) cp_async16(sb + SB(0) + soffB[j], weight + boff[j]);
    CP_COMMIT();

    for (int kc = 0; kc < NKC; kc++) {
        const int cur = kc & 1;
        if (kc + 1 < NKC) {
            const int nxt = cur ^ 1;
            const uint32_t kadd = (uint32_t)(kc + 1) * KC;
#pragma unroll
            for (int j = 0; j < 2; j++)
                cp_async16(sb + SA(nxt) + soffA[j], g_hbf + aoff[j] + kadd);
#pragma unroll
            for (int j = 0; j < 8; j++)
                cp_async16(sb + SB(nxt) + soffB[j], weight + boff[j] + kadd);
            CP_COMMIT();
            CP_WAIT(1);
        } else {
            CP_WAIT(0);
        }
        __syncthreads();
#pragma unroll
        for (int ks = 0; ks < 2; ks++) {     // 2 x k16 per chunk
            // A frags via ldmatrix (paired-row swizzled bf16)
            uint32_t af[4][4];
#pragma unroll
            for (int mi = 0; mi < 4; mi++) {
                int r  = wm * 64 + mi * 16 + (lane & 15);
                uint32_t kbyte = (uint32_t)(ks * 32 + ((lane >> 4) << 4));
                uint32_t o = (uint32_t)((r >> 1) * 128 + (r & 1) * 64) + kbyte;
                lds_frag4(af[mi], sb + SA(cur) + SW(o));
            }
            // B frags: ld.shared.v2.f32 + cvt to bf16x2 (mma-native layout).
            // Full in-row offset computed BEFORE the swizzle XOR.
            uint32_t bf[4][4];
            const uint32_t c0 = c8 + (uint32_t)(ks * 64);
#pragma unroll
            for (int np = 0; np < 4; np++) {
                uint32_t base = sb + SB(cur) + brow[np];
                uint32_t X = bX[np];
                float2 v0 = lds_f2(base + (c0 ^ X));
                float2 v1 = lds_f2(base + ((c0 + 32) ^ X));
                float2 v2 = lds_f2(base + 1024 + (c0 ^ X));
                float2 v3 = lds_f2(base + 1024 + ((c0 + 32) ^ X));
                bf[np][0] = pack_bf16(v0.x, v0.y);
                bf[np][1] = pack_bf16(v1.x, v1.y);
                bf[np][2] = pack_bf16(v2.x, v2.y);
                bf[np][3] = pack_bf16(v3.x, v3.y);
            }
#pragma unroll
            for (int mi = 0; mi < 4; mi++)
#pragma unroll
                for (int nj = 0; nj < 8; nj++)
                    mma16816(acc[mi][nj], af[mi],
                             bf[nj >> 1][(nj & 1) * 2], bf[nj >> 1][(nj & 1) * 2 + 1]);
        }
        __syncthreads();
    }

    // ---- epilogue: exp(logit + bias), reduce to per-row sums ----
    const float* bs = reinterpret_cast<const float*>(smem + SBIAS);
    float* rowsum = reinterpret_cast<float*>(smem + SROW);
    float loc[8];
#pragma unroll
    for (int i = 0; i < 8; i++) loc[i] = 0.0f;
#pragma unroll
    for (int mi = 0; mi < 4; mi++) {
#pragma unroll
        for (int nj = 0; nj < 8; nj++) {
            int c = wn * 64 + nj * 8 + 2 * (lane & 3);
            float b0 = bs[c], b1 = bs[c + 1];
            loc[2*mi]   += __expf(acc[mi][nj][0] + b0) + __expf(acc[mi][nj][1] + b1);
            loc[2*mi+1] += __expf(acc[mi][nj][2] + b0) + __expf(acc[mi][nj][3] + b1);
        }
    }
#pragma unroll
    for (int i = 0; i < 8; i++) {
        loc[i] += __shfl_xor_sync(0xffffffffu, loc[i], 1);
        loc[i] += __shfl_xor_sync(0xffffffffu, loc[i], 2);
    }
    if ((lane & 3) == 0) {
        int g = lane >> 2;
#pragma unroll
        for (int mi = 0; mi < 4; mi++) {
            atomicAdd(&rowsum[wm * 64 + mi * 16 + g],     loc[2*mi]);
            atomicAdd(&rowsum[wm * 64 + mi * 16 + g + 8], loc[2*mi+1]);
        }
    }
    __syncthreads();
    if (tid < TM && row0 + tid < count)
        atomicAdd(&g_S[region][listp[tid]], rowsum[tid]);
}

// ---------------- kernel 3: finalize NLL ----------------
__global__ void finalize_kernel(float* __restrict__ out) {
    int t = blockIdx.x * blockDim.x + threadIdx.x;
    if (t >= NTOK) return;
    int r = g_cid[t];
    float ch = __expf(g_clogit[t][0]) + __expf(g_clogit[t][1]) + __expf(g_clogit[t][2]);
    float lse_head = __logf(g_S[0][t] + ch);
    float nll;
    if (r == 0) {
        nll = lse_head - g_tlogit[t];
    } else {
        float lse_tail = __logf(g_S[r][t]);
        // reference: head_logprob[:, -i] for region i -> cluster column (3 - i)
        nll = lse_head + lse_tail - g_clogit[t][3 - r] - g_tlogit[t];
    }
    out[t] = nll;
}

// ---------------- launcher ----------------
extern "C" void kernel_launch(void* const* d_in, const int* in_sizes, int n_in,
                              void* d_out, int out_size) {
    const float* hidden = (const float*)d_in[0];
    const int*   target = (const int*)d_in[1];
    const float* weight = (const float*)d_in[2];
    const float* bias   = (const float*)d_in[3];
    const float* cw     = (const float*)d_in[4];
    const float* cb     = (const float*)d_in[5];
    float* out = (float*)d_out;

    cudaFuncSetAttribute(gemm_sumexp,
                         cudaFuncAttributeMaxDynamicSharedMemorySize, SMEM_TOTAL);

    zero_kernel<<<1, 256>>>();
    prep_kernel<<<128, 256>>>(hidden, target, weight, bias, cw, cb);

    // bf16 hidden only (tiny); weight stays f32 and is converted in-register in the GEMM
    __nv_bfloat16* d_hbf = nullptr; cudaGetSymbolAddress((void**)&d_hbf, g_hbf);
    const size_t h8 = (size_t)NTOK * DIN / 8;           // 131,072
    convert_kernel<<<(unsigned)((h8 + 255) / 256), 256>>>(hidden, d_hbf, h8);

    // one merged launch over all regions; M-tiles fastest
    gemm_sumexp<<<dim3(8, NT_TOTAL), GT, SMEM_TOTAL>>>(weight, bias);

    finalize_kernel<<<4, 256>>>(out);
}

// round 11
// speedup vs baseline: 1.0512x; 1.0512x over previous
#include <cuda_runtime.h>
#include <cuda_bf16.h>
#include <cstdint>

// ---------------- problem constants ----------------
#define NTOK 1024
#define DIN  1024
#define NCLS 267735
#define WELEMS ((size_t)NCLS * DIN)          // 274,160,640
// regions: [0,20000) head, [20000,40000), [40000,200000), [200000,267735)

// ---------------- GEMM tile config ----------------
#define TM 128
#define TN 256
#define KC 64
#define NKC 16              // DIN / KC
#define GT 512              // 16 warps: 4 M-warps x 4 N-warps, warp tile 32x64

// N-tile counts per region (classes / TN, ceil)
#define NT0 79
#define NT1 79
#define NT2 625
#define NT3 265
#define NT_TOTAL (NT0 + NT1 + NT2 + NT3)   // 1048

// smem byte offsets. A: 2 x 16KB, B: 2 x 32KB (bf16, 128B rows, SW128)
#define SA(buf) ((buf) * 16384)
#define SB(buf) (32768 + (buf) * 32768)
#define SBIAS 98304                          // 256 f32
#define SLIST 99328                          // 128 int
#define SROW  99840                          // 128 f32
#define SMEM_TOTAL 100352

#define SW(o) ((o) ^ (((o) >> 3) & 0x70))    // SW128 swizzle on byte offsets

// ---------------- device scratch (static; no allocation) ----------------
__device__ __nv_bfloat16 g_wbf[WELEMS];      // bf16 weight (548 MB)
__device__ __nv_bfloat16 g_hbf[NTOK * DIN];  // bf16 hidden
__device__ float g_S[4][NTOK];
__device__ int   g_list[4][NTOK];
__device__ int   g_count[4];
__device__ float g_tlogit[NTOK];
__device__ float g_clogit[NTOK][3];
__device__ int   g_cid[NTOK];

// ---------------- small helpers ----------------
__device__ __forceinline__ uint32_t smem_u32(const void* p) {
    uint32_t a;
    asm("{ .reg .u64 t; cvta.to.shared.u64 t, %1; cvt.u32.u64 %0, t; }" : "=r"(a) : "l"(p));
    return a;
}
__device__ __forceinline__ uint32_t pack_bf16(float lo, float hi) {
    __nv_bfloat162 h = __floats2bfloat162_rn(lo, hi);
    return *reinterpret_cast<uint32_t*>(&h);
}
__device__ __forceinline__ void cp_async16(uint32_t saddr, const void* gaddr) {
    asm volatile("cp.async.cg.shared.global [%0], [%1], 16;" :: "r"(saddr), "l"(gaddr));
}
#define CP_COMMIT() asm volatile("cp.async.commit_group;" ::: "memory")
#define CP_WAIT(n)  asm volatile("cp.async.wait_group %0;" :: "n"(n) : "memory")
__device__ __forceinline__ void lds_frag4(uint32_t r[4], uint32_t addr) {
    asm volatile("ldmatrix.sync.aligned.m8n8.x4.shared.b16 {%0,%1,%2,%3}, [%4];"
        : "=r"(r[0]), "=r"(r[1]), "=r"(r[2]), "=r"(r[3]) : "r"(addr));
}
__device__ __forceinline__ void mma16816(float d[4], const uint32_t a[4],
                                         uint32_t b0, uint32_t b1) {
    asm volatile("mma.sync.aligned.m16n8k16.row.col.f32.bf16.bf16.f32 "
        "{%0,%1,%2,%3}, {%4,%5,%6,%7}, {%8,%9}, {%0,%1,%2,%3};"
        : "+f"(d[0]), "+f"(d[1]), "+f"(d[2]), "+f"(d[3])
        : "r"(a[0]), "r"(a[1]), "r"(a[2]), "r"(a[3]), "r"(b0), "r"(b1));
}

// ---------------- kernel 0: reset scratch ----------------
__global__ void zero_kernel() {
    int t = threadIdx.x;
    for (int i = t; i < 4 * NTOK; i += blockDim.x) (&g_S[0][0])[i] = 0.0f;
    for (int i = t; i < NTOK; i += blockDim.x) g_list[0][i] = i;
    if (t == 0) g_count[0] = NTOK;
    if (t >= 1 && t < 4) g_count[t] = 0;
}

// ---------------- f32 -> bf16 streaming convert (8 elems / thread) ----------------
__global__ void convert_kernel(const float* __restrict__ src,
                               __nv_bfloat16* __restrict__ dst, size_t n8) {
    size_t i = (size_t)blockIdx.x * blockDim.x + threadIdx.x;
    if (i >= n8) return;
    const float4* p = reinterpret_cast<const float4*>(src) + i * 2;
    float4 a = p[0], b = p[1];
    uint4 o;
    o.x = pack_bf16(a.x, a.y); o.y = pack_bf16(a.z, a.w);
    o.z = pack_bf16(b.x, b.y); o.w = pack_bf16(b.z, b.w);
    reinterpret_cast<uint4*>(dst)[i] = o;
}

// ---------------- kernel 1: per-token prep (exact f32 dots + compaction) ----------------
__global__ void prep_kernel(const float* __restrict__ hidden,
                            const int* __restrict__ target,   // int32 (JAX x64 disabled)
                            const float* __restrict__ weight,
                            const float* __restrict__ bias,
                            const float* __restrict__ cw,
                            const float* __restrict__ cb) {
    int gw = (int)((blockIdx.x * blockDim.x + threadIdx.x) >> 5);
    int lane = threadIdx.x & 31;
    if (gw >= NTOK) return;
    const int t = target[gw];
    const float4* h4  = reinterpret_cast<const float4*>(hidden + (size_t)gw * DIN);
    const float4* w4  = reinterpret_cast<const float4*>(weight + (size_t)t * DIN);
    const float4* c40 = reinterpret_cast<const float4*>(cw);
    const float4* c41 = reinterpret_cast<const float4*>(cw + DIN);
    const float4* c42 = reinterpret_cast<const float4*>(cw + 2 * DIN);
    float at = 0.f, a0 = 0.f, a1 = 0.f, a2 = 0.f;
#pragma unroll
    for (int j = 0; j < 8; j++) {
        int i = lane + 32 * j;
        float4 h = h4[i];
        float4 w = w4[i];
        at += h.x * w.x + h.y * w.y + h.z * w.z + h.w * w.w;
        float4 q = c40[i]; a0 += h.x * q.x + h.y * q.y + h.z * q.z + h.w * q.w;
        q = c41[i];        a1 += h.x * q.x + h.y * q.y + h.z * q.z + h.w * q.w;
        q = c42[i];        a2 += h.x * q.x + h.y * q.y + h.z * q.z + h.w * q.w;
    }
#pragma unroll
    for (int o = 16; o > 0; o >>= 1) {
        at += __shfl_xor_sync(0xffffffffu, at, o);
        a0 += __shfl_xor_sync(0xffffffffu, a0, o);
        a1 += __shfl_xor_sync(0xffffffffu, a1, o);
        a2 += __shfl_xor_sync(0xffffffffu, a2, o);
    }
    if (lane == 0) {
        g_tlogit[gw] = at + bias[t];
        g_clogit[gw][0] = a0 + cb[0];
        g_clogit[gw][1] = a1 + cb[1];
        g_clogit[gw][2] = a2 + cb[2];
        int r = (t < 20000) ? 0 : (t < 40000) ? 1 : (t < 200000) ? 2 : 3;
        g_cid[gw] = r;
        if (r > 0) {
            int idx = atomicAdd(&g_count[r], 1);
            g_list[r][idx] = gw;
        }
    }
}

// ---------------- kernel 2: merged bf16 HMMA GEMM (cp.async, 16 warps) ----------------
// A: 1024 x 16B ops (2/thread). B: 2048 x 16B ops (4/thread). Warp tile 32x64.
__global__ __launch_bounds__(GT, 1)
void gemm_sumexp(const float* __restrict__ bias) {
    extern __shared__ char smem[];
    const int tid = threadIdx.x;

    int nt = blockIdx.y;
    int region, lo, width;
    if (nt < NT0)                  { region = 0; lo = 0;      width = 20000;  }
    else if (nt < NT0 + NT1)       { region = 1; lo = 20000;  width = 20000;  nt -= NT0; }
    else if (nt < NT0 + NT1 + NT2) { region = 2; lo = 40000;  width = 160000; nt -= NT0 + NT1; }
    else                           { region = 3; lo = 200000; width = 67735;  nt -= NT0 + NT1 + NT2; }

    const int count = g_count[region];
    const int row0 = blockIdx.x * TM;        // M fastest -> weight-tile sharers concurrent
    if (row0 >= count) return;
    const int col0 = nt * TN;
    const uint32_t sb = smem_u32(smem);

    if (tid < TM) {
        int rr = row0 + tid;
        if (rr > count - 1) rr = count - 1;
        reinterpret_cast<int*>(smem + SLIST)[tid] = g_list[region][rr];
        reinterpret_cast<float*>(smem + SROW)[tid] = 0.0f;
    }
    if (tid >= TM && tid < TM + TN) {        // bias tile
        int c = tid - TM;
        int cls = col0 + c;
        reinterpret_cast<float*>(smem + SBIAS)[c] =
            (cls < width) ? bias[lo + cls] : __int_as_float(0xff800000);  // -inf
    }
    __syncthreads();

    const int* listp = reinterpret_cast<const int*>(smem + SLIST);
    const int lane = tid & 31, wid = tid >> 5;

    // ---- cp.async mappings (chunk-invariant) ----
    const int lrow = tid >> 2;               // 0..127
    const int unit0 = tid & 3;               // base 16B unit
    uint32_t aoff[2], soffA[2];
#pragma unroll
    for (int j = 0; j < 2; j++) {
        int u = unit0 + j * 4;               // 0..7
        aoff[j] = (uint32_t)listp[lrow] * DIN + u * 8;
        soffA[j] = SW((uint32_t)(lrow * 128 + u * 16));
    }
    uint32_t boff[4], soffB[4];
#pragma unroll
    for (int j = 0; j < 4; j++) {
        int r = lrow + (j >> 1) * 128;       // 0..255
        int u = unit0 + (j & 1) * 4;         // 0..7
        int cls = col0 + r;
        boff[j] = (uint32_t)(lo + ((cls < width) ? cls : width - 1)) * DIN + u * 8;
        soffB[j] = SW((uint32_t)(r * 128 + u * 16));
    }

    const int wm = wid & 3, wn = wid >> 2;   // 4 M-warps x 4 N-warps

    float acc[2][8][4];
#pragma unroll
    for (int mi = 0; mi < 2; mi++)
#pragma unroll
        for (int nj = 0; nj < 8; nj++)
#pragma unroll
            for (int e = 0; e < 4; e++) acc[mi][nj][e] = 0.0f;

    // ---- async load of chunk 0 ----
#pragma unroll
    for (int j = 0; j < 2; j++) cp_async16(sb + SA(0) + soffA[j], g_hbf + aoff[j]);
#pragma unroll
    for (int j = 0; j < 4; j++) cp_async16(sb + SB(0) + soffB[j], g_wbf + boff[j]);
    CP_COMMIT();

    for (int kc = 0; kc < NKC; kc++) {
        const int cur = kc & 1;
        if (kc + 1 < NKC) {
            const int nxt = cur ^ 1;
            const uint32_t kadd = (uint32_t)(kc + 1) * KC;
#pragma unroll
            for (int j = 0; j < 2; j++)
                cp_async16(sb + SA(nxt) + soffA[j], g_hbf + aoff[j] + kadd);
#pragma unroll
            for (int j = 0; j < 4; j++)
                cp_async16(sb + SB(nxt) + soffB[j], g_wbf + boff[j] + kadd);
            CP_COMMIT();
            CP_WAIT(1);
        } else {
            CP_WAIT(0);
        }
        __syncthreads();
#pragma unroll
        for (int ks = 0; ks < 4; ks++) {       // 4 x k16 per chunk
            uint32_t af[2][4];
#pragma unroll
            for (int mi = 0; mi < 2; mi++) {
                int r  = wm * 32 + mi * 16 + (lane & 15);
                int kb = ks * 16 + ((lane >> 4) << 3);
                lds_frag4(af[mi], sb + SA(cur) + SW((uint32_t)(r * 128 + kb * 2)));
            }
            uint32_t bf[4][4];
#pragma unroll
            for (int np = 0; np < 4; np++) {
                int cl = wn * 64 + np * 16 + (lane & 7) + ((lane & 16) ? 8 : 0);
                int kb = ks * 16 + ((lane & 8) ? 8 : 0);
                lds_frag4(bf[np], sb + SB(cur) + SW((uint32_t)(cl * 128 + kb * 2)));
            }
#pragma unroll
            for (int mi = 0; mi < 2; mi++)
#pragma unroll
                for (int nj = 0; nj < 8; nj++)
                    mma16816(acc[mi][nj], af[mi],
                             bf[nj >> 1][(nj & 1) * 2], bf[nj >> 1][(nj & 1) * 2 + 1]);
        }
        __syncthreads();
    }

    // ---- epilogue: exp(logit + bias), reduce to per-row sums ----
    const float* bs = reinterpret_cast<const float*>(smem + SBIAS);
    float* rowsum = reinterpret_cast<float*>(smem + SROW);
    float loc[4];
#pragma unroll
    for (int i = 0; i < 4; i++) loc[i] = 0.0f;
#pragma unroll
    for (int mi = 0; mi < 2; mi++) {
#pragma unroll
        for (int nj = 0; nj < 8; nj++) {
            int c = wn * 64 + nj * 8 + 2 * (lane & 3);
            float b0 = bs[c], b1 = bs[c + 1];
            loc[2*mi]   += __expf(acc[mi][nj][0] + b0) + __expf(acc[mi][nj][1] + b1);
            loc[2*mi+1] += __expf(acc[mi][nj][2] + b0) + __expf(acc[mi][nj][3] + b1);
        }
    }
#pragma unroll
    for (int i = 0; i < 4; i++) {
        loc[i] += __shfl_xor_sync(0xffffffffu, loc[i], 1);
        loc[i] += __shfl_xor_sync(0xffffffffu, loc[i], 2);
    }
    if ((lane & 3) == 0) {
        int g = lane >> 2;
#pragma unroll
        for (int mi = 0; mi < 2; mi++) {
            atomicAdd(&rowsum[wm * 32 + mi * 16 + g],     loc[2*mi]);
            atomicAdd(&rowsum[wm * 32 + mi * 16 + g + 8], loc[2*mi+1]);
        }
    }
    __syncthreads();
    if (tid < TM && row0 + tid < count)
        atomicAdd(&g_S[region][listp[tid]], rowsum[tid]);
}

// ---------------- kernel 3: finalize NLL ----------------
__global__ void finalize_kernel(float* __restrict__ out) {
    int t = blockIdx.x * blockDim.x + threadIdx.x;
    if (t >= NTOK) return;
    int r = g_cid[t];
    float ch = __expf(g_clogit[t][0]) + __expf(g_clogit[t][1]) + __expf(g_clogit[t][2]);
    float lse_head = __logf(g_S[0][t] + ch);
    float nll;
    if (r == 0) {
        nll = lse_head - g_tlogit[t];
    } else {
        float lse_tail = __logf(g_S[r][t]);
        // reference: head_logprob[:, -i] for region i -> cluster column (3 - i)
        nll = lse_head + lse_tail - g_clogit[t][3 - r] - g_tlogit[t];
    }
    out[t] = nll;
}

// ---------------- launcher ----------------
extern "C" void kernel_launch(void* const* d_in, const int* in_sizes, int n_in,
                              void* d_out, int out_size) {
    const float* hidden = (const float*)d_in[0];
    const int*   target = (const int*)d_in[1];
    const float* weight = (const float*)d_in[2];
    const float* bias   = (const float*)d_in[3];
    const float* cw     = (const float*)d_in[4];
    const float* cb     = (const float*)d_in[5];
    float* out = (float*)d_out;

    cudaFuncSetAttribute(gemm_sumexp,
                         cudaFuncAttributeMaxDynamicSharedMemorySize, SMEM_TOTAL);

    zero_kernel<<<1, 256>>>();
    prep_kernel<<<128, 256>>>(hidden, target, weight, bias, cw, cb);

    // bf16 pre-conversion into static buffers (pure function of inputs)
    __nv_bfloat16* d_wbf = nullptr; cudaGetSymbolAddress((void**)&d_wbf, g_wbf);
    __nv_bfloat16* d_hbf = nullptr; cudaGetSymbolAddress((void**)&d_hbf, g_hbf);
    const size_t w8 = WELEMS / 8;                       // 34,270,080
    convert_kernel<<<(unsigned)((w8 + 255) / 256), 256>>>(weight, d_wbf, w8);
    const size_t h8 = (size_t)NTOK * DIN / 8;           // 131,072
    convert_kernel<<<(unsigned)((h8 + 255) / 256), 256>>>(hidden, d_hbf, h8);

    // one merged launch over all regions; M-tiles fastest
    gemm_sumexp<<<dim3(8, NT_TOTAL), GT, SMEM_TOTAL>>>(bias);

    finalize_kernel<<<4, 256>>>(out);
}

// round 13
// speedup vs baseline: 1.1578x; 1.1014x over previous
#include <cuda_runtime.h>
#include <cuda_bf16.h>
#include <cstdint>

// ---------------- problem constants ----------------
#define NTOK 1024
#define DIN  1024
#define NCLS 267735
#define WELEMS ((size_t)NCLS * DIN)          // 274,160,640
// regions: [0,20000) head, [20000,40000), [40000,200000), [200000,267735)

// ---------------- GEMM tile config ----------------
#define TM 128
#define TN 256
#define KC 64
#define NKC 16              // DIN / KC
#define GT 256              // 8 warps: 2 M-warps x 4 N-warps, warp tile 64x64

// N-tile counts per region (classes / TN, ceil)
#define NT0 79
#define NT1 79
#define NT2 625
#define NT3 265
#define NT_TOTAL (NT0 + NT1 + NT2 + NT3)   // 1048

// smem byte offsets. A: 2 x 16KB, B: 2 x 32KB (bf16, 128B rows, SW128)
#define SA(buf) ((buf) * 16384)
#define SB(buf) (32768 + (buf) * 32768)
#define SBIAS 98304                          // 256 f32
#define SLIST 99328                          // 128 int
#define SROW  99840                          // 128 f32
#define SMEM_TOTAL 100352

#define SW(o) ((o) ^ (((o) >> 3) & 0x70))    // SW128 swizzle on byte offsets

// ---------------- device scratch (static; no allocation) ----------------
__device__ __nv_bfloat16 g_wbf[WELEMS];      // bf16 weight (548 MB), written by conv_gemm
__device__ __nv_bfloat16 g_hbf[NTOK * DIN];  // bf16 hidden
__device__ float g_S[4][NTOK];
__device__ int   g_list[4][NTOK];
__device__ int   g_count[4];
__device__ float g_tlogit[NTOK];
__device__ float g_clogit[NTOK][3];
__device__ int   g_cid[NTOK];

// ---------------- small helpers ----------------
__device__ __forceinline__ uint32_t smem_u32(const void* p) {
    uint32_t a;
    asm("{ .reg .u64 t; cvta.to.shared.u64 t, %1; cvt.u32.u64 %0, t; }" : "=r"(a) : "l"(p));
    return a;
}
__device__ __forceinline__ uint32_t pack_bf16(float lo, float hi) {
    __nv_bfloat162 h = __floats2bfloat162_rn(lo, hi);
    return *reinterpret_cast<uint32_t*>(&h);
}
__device__ __forceinline__ void cp_async16(uint32_t saddr, const void* gaddr) {
    asm volatile("cp.async.cg.shared.global [%0], [%1], 16;" :: "r"(saddr), "l"(gaddr));
}
#define CP_COMMIT() asm volatile("cp.async.commit_group;" ::: "memory")
#define CP_WAIT(n)  asm volatile("cp.async.wait_group %0;" :: "n"(n) : "memory")
__device__ __forceinline__ void lds_frag4(uint32_t r[4], uint32_t addr) {
    asm volatile("ldmatrix.sync.aligned.m8n8.x4.shared.b16 {%0,%1,%2,%3}, [%4];"
        : "=r"(r[0]), "=r"(r[1]), "=r"(r[2]), "=r"(r[3]) : "r"(addr));
}
__device__ __forceinline__ void sts64(uint32_t addr, uint2 v) {
    asm volatile("st.shared.v2.u32 [%0], {%1,%2};" :: "r"(addr), "r"(v.x), "r"(v.y) : "memory");
}
__device__ __forceinline__ void mma16816(float d[4], const uint32_t a[4],
                                         uint32_t b0, uint32_t b1) {
    asm volatile("mma.sync.aligned.m16n8k16.row.col.f32.bf16.bf16.f32 "
        "{%0,%1,%2,%3}, {%4,%5,%6,%7}, {%8,%9}, {%0,%1,%2,%3};"
        : "+f"(d[0]), "+f"(d[1]), "+f"(d[2]), "+f"(d[3])
        : "r"(a[0]), "r"(a[1]), "r"(a[2]), "r"(a[3]), "r"(b0), "r"(b1));
}

// region mapping from concatenated N-tile index
__device__ __forceinline__ void region_map(int nt_in, int& region, int& lo, int& width, int& nt) {
    nt = nt_in;
    if (nt < NT0)                  { region = 0; lo = 0;      width = 20000;  }
    else if (nt < NT0 + NT1)       { region = 1; lo = 20000;  width = 20000;  nt -= NT0; }
    else if (nt < NT0 + NT1 + NT2) { region = 2; lo = 40000;  width = 160000; nt -= NT0 + NT1; }
    else                           { region = 3; lo = 200000; width = 67735;  nt -= NT0 + NT1 + NT2; }
}

// ---------------- kernel 0: reset scratch ----------------
__global__ void zero_kernel() {
    int t = threadIdx.x;
    for (int i = t; i < 4 * NTOK; i += blockDim.x) (&g_S[0][0])[i] = 0.0f;
    for (int i = t; i < NTOK; i += blockDim.x) g_list[0][i] = i;
    if (t == 0) g_count[0] = NTOK;
    if (t >= 1 && t < 4) g_count[t] = 0;
}

// ---------------- f32 -> bf16 streaming convert (hidden; 8 elems / thread) ----------------
__global__ void convert_kernel(const float* __restrict__ src,
                               __nv_bfloat16* __restrict__ dst, size_t n8) {
    size_t i = (size_t)blockIdx.x * blockDim.x + threadIdx.x;
    if (i >= n8) return;
    const float4* p = reinterpret_cast<const float4*>(src) + i * 2;
    float4 a = p[0], b = p[1];
    uint4 o;
    o.x = pack_bf16(a.x, a.y); o.y = pack_bf16(a.z, a.w);
    o.z = pack_bf16(b.x, b.y); o.w = pack_bf16(b.z, b.w);
    reinterpret_cast<uint4*>(dst)[i] = o;
}

// ---------------- kernel 1: per-token prep (exact f32 dots + compaction) ----------------
__global__ void prep_kernel(const float* __restrict__ hidden,
                            const int* __restrict__ target,   // int32 (JAX x64 disabled)
                            const float* __restrict__ weight,
                            const float* __restrict__ bias,
                            const float* __restrict__ cw,
                            const float* __restrict__ cb) {
    int gw = (int)((blockIdx.x * blockDim.x + threadIdx.x) >> 5);
    int lane = threadIdx.x & 31;
    if (gw >= NTOK) return;
    const int t = target[gw];
    const float4* h4  = reinterpret_cast<const float4*>(hidden + (size_t)gw * DIN);
    const float4* w4  = reinterpret_cast<const float4*>(weight + (size_t)t * DIN);
    const float4* c40 = reinterpret_cast<const float4*>(cw);
    const float4* c41 = reinterpret_cast<const float4*>(cw + DIN);
    const float4* c42 = reinterpret_cast<const float4*>(cw + 2 * DIN);
    float at = 0.f, a0 = 0.f, a1 = 0.f, a2 = 0.f;
#pragma unroll
    for (int j = 0; j < 8; j++) {
        int i = lane + 32 * j;
        float4 h = h4[i];
        float4 w = w4[i];
        at += h.x * w.x + h.y * w.y + h.z * w.z + h.w * w.w;
        float4 q = c40[i]; a0 += h.x * q.x + h.y * q.y + h.z * q.z + h.w * q.w;
        q = c41[i];        a1 += h.x * q.x + h.y * q.y + h.z * q.z + h.w * q.w;
        q = c42[i];        a2 += h.x * q.x + h.y * q.y + h.z * q.z + h.w * q.w;
    }
#pragma unroll
    for (int o = 16; o > 0; o >>= 1) {
        at += __shfl_xor_sync(0xffffffffu, at, o);
        a0 += __shfl_xor_sync(0xffffffffu, a0, o);
        a1 += __shfl_xor_sync(0xffffffffu, a1, o);
        a2 += __shfl_xor_sync(0xffffffffu, a2, o);
    }
    if (lane == 0) {
        g_tlogit[gw] = at + bias[t];
        g_clogit[gw][0] = a0 + cb[0];
        g_clogit[gw][1] = a1 + cb[1];
        g_clogit[gw][2] = a2 + cb[2];
        int r = (t < 20000) ? 0 : (t < 40000) ? 1 : (t < 200000) ? 2 : 3;
        g_cid[gw] = r;
        if (r > 0) {
            int idx = atomicAdd(&g_count[r], 1);
            g_list[r][idx] = gw;
        }
    }
}

// ---------------- shared epilogue ----------------
__device__ __forceinline__ void epilogue(char* smem, float acc[4][8][4],
                                         int wm, int wn, int lane, int tid,
                                         int region, int row0, int count,
                                         const int* listp) {
    const float* bs = reinterpret_cast<const float*>(smem + SBIAS);
    float* rowsum = reinterpret_cast<float*>(smem + SROW);
    float loc[8];
#pragma unroll
    for (int i = 0; i < 8; i++) loc[i] = 0.0f;
#pragma unroll
    for (int mi = 0; mi < 4; mi++) {
#pragma unroll
        for (int nj = 0; nj < 8; nj++) {
            int c = wn * 64 + nj * 8 + 2 * (lane & 3);
            float b0 = bs[c], b1 = bs[c + 1];
            loc[2*mi]   += __expf(acc[mi][nj][0] + b0) + __expf(acc[mi][nj][1] + b1);
            loc[2*mi+1] += __expf(acc[mi][nj][2] + b0) + __expf(acc[mi][nj][3] + b1);
        }
    }
#pragma unroll
    for (int i = 0; i < 8; i++) {
        loc[i] += __shfl_xor_sync(0xffffffffu, loc[i], 1);
        loc[i] += __shfl_xor_sync(0xffffffffu, loc[i], 2);
    }
    if ((lane & 3) == 0) {
        int g = lane >> 2;
#pragma unroll
        for (int mi = 0; mi < 4; mi++) {
            atomicAdd(&rowsum[wm * 64 + mi * 16 + g],     loc[2*mi]);
            atomicAdd(&rowsum[wm * 64 + mi * 16 + g + 8], loc[2*mi+1]);
        }
    }
    __syncthreads();
    if (tid < TM && row0 + tid < count)
        atomicAdd(&g_S[region][listp[tid]], rowsum[tid]);
}

// ---------------- kernel 2a: M-tile-0 GEMM fused with weight f32->bf16 convert ----------------
// B tile staged by LDG.128 f32 -> cvt -> STS bf16; bf16 also written back to g_wbf.
__global__ __launch_bounds__(GT, 1)
void conv_gemm_sumexp(const float* __restrict__ weight,
                      const float* __restrict__ bias) {
    extern __shared__ char smem[];
    const int tid = threadIdx.x;
    int region, lo, width, nt;
    region_map(blockIdx.y, region, lo, width, nt);
    const int count = g_count[region];
    const int row0 = 0;
    const int col0 = nt * TN;
    const uint32_t sb = smem_u32(smem);

    if (tid < TM) {
        int rr = tid;
        if (rr > count - 1) rr = count - 1;
        reinterpret_cast<int*>(smem + SLIST)[tid] = g_list[region][rr];
        reinterpret_cast<float*>(smem + SROW)[tid] = 0.0f;
    }
    if (tid >= TM && tid < TM + TN) {
        int c = tid - TM;
        int cls = col0 + c;
        reinterpret_cast<float*>(smem + SBIAS)[c] =
            (cls < width) ? bias[lo + cls] : __int_as_float(0xff800000);  // -inf
    }
    __syncthreads();

    const int* listp = reinterpret_cast<const int*>(smem + SLIST);
    const int lane = tid & 31, wid = tid >> 5;

    // A (bf16) cp.async mapping — R8's exact 4-op form: full 16KB tile coverage
    const int sub = lane >> 3;               // row within 4-row group
    const int pos = lane & 7;                // 16B unit within 128B row
    uint32_t aoff[4], soffA[4];
#pragma unroll
    for (int j = 0; j < 4; j++) {
        int r = wid * 16 + j * 4 + sub;      // 0..127
        aoff[j] = (uint32_t)listp[r] * DIN + pos * 8;
        soffA[j] = SW((uint32_t)(r * 128 + pos * 16));
    }

    // B staging mapping: row = o*16 + (tid>>4); ucol = tid&15 (4 f32 elems per op)
    const int rhi = tid >> 4, ucol = tid & 15;
    uint32_t goff[16], sboff[16];
#pragma unroll
    for (int o = 0; o < 16; o++) {
        int row = o * 16 + rhi;              // 0..255
        int cls = col0 + row;
        if (cls >= width) cls = width - 1;   // clamp (dup writes of same data: benign)
        goff[o] = (uint32_t)(lo + cls) * DIN + ucol * 4;    // element offset (f32 & bf16)
        sboff[o] = SW((uint32_t)(row * 128 + ucol * 8));
    }

    const int wm = wid & 1, wn = wid >> 1;

    float acc[4][8][4];
#pragma unroll
    for (int mi = 0; mi < 4; mi++)
#pragma unroll
        for (int nj = 0; nj < 8; nj++)
#pragma unroll
            for (int e = 0; e < 4; e++) acc[mi][nj][e] = 0.0f;

    for (int kc = 0; kc < NKC; kc++) {
        const uint32_t kadd = (uint32_t)kc * KC;
        // A async into buffer 0
#pragma unroll
        for (int j = 0; j < 4; j++)
            cp_async16(sb + SA(0) + soffA[j], g_hbf + aoff[j] + kadd);
        CP_COMMIT();
        // B: two bursts of 8 x (LDG.128 f32 -> cvt -> STS.64 + STG.64 writeback)
#pragma unroll
        for (int h = 0; h < 2; h++) {
            float4 v[8];
#pragma unroll
            for (int j = 0; j < 8; j++)
                v[j] = *reinterpret_cast<const float4*>(weight + goff[h * 8 + j] + kadd);
#pragma unroll
            for (int j = 0; j < 8; j++) {
                uint2 p;
                p.x = pack_bf16(v[j].x, v[j].y);
                p.y = pack_bf16(v[j].z, v[j].w);
                sts64(sb + SB(0) + sboff[h * 8 + j], p);
                *reinterpret_cast<uint2*>(g_wbf + goff[h * 8 + j] + kadd) = p;
            }
        }
        CP_WAIT(0);
        __syncthreads();
#pragma unroll
        for (int ks = 0; ks < 4; ks++) {
            uint32_t afr[4][4];
#pragma unroll
            for (int mi = 0; mi < 4; mi++) {
                int r  = wm * 64 + mi * 16 + (lane & 15);
                int kb = ks * 16 + ((lane >> 4) << 3);
                lds_frag4(afr[mi], sb + SA(0) + SW((uint32_t)(r * 128 + kb * 2)));
            }
            uint32_t bfr[4][4];
#pragma unroll
            for (int np = 0; np < 4; np++) {
                int cl = wn * 64 + np * 16 + (lane & 7) + ((lane & 16) ? 8 : 0);
                int kb = ks * 16 + ((lane & 8) ? 8 : 0);
                lds_frag4(bfr[np], sb + SB(0) + SW((uint32_t)(cl * 128 + kb * 2)));
            }
#pragma unroll
            for (int mi = 0; mi < 4; mi++)
#pragma unroll
                for (int nj = 0; nj < 8; nj++)
                    mma16816(acc[mi][nj], afr[mi],
                             bfr[nj >> 1][(nj & 1) * 2], bfr[nj >> 1][(nj & 1) * 2 + 1]);
        }
        __syncthreads();
    }

    epilogue(smem, acc, wm, wn, lane, tid, region, row0, count, listp);
}

// ---------------- kernel 2b: M-tiles 1..7 GEMM (bf16 cp.async, R8 path) ----------------
__global__ __launch_bounds__(GT, 1)
void gemm_sumexp(const float* __restrict__ bias) {
    extern __shared__ char smem[];
    const int tid = threadIdx.x;
    int region, lo, width, nt;
    region_map(blockIdx.y, region, lo, width, nt);
    const int count = g_count[region];
    const int row0 = (blockIdx.x + 1) * TM;  // M-tiles 1..7
    if (row0 >= count) return;
    const int col0 = nt * TN;
    const uint32_t sb = smem_u32(smem);

    if (tid < TM) {
        int rr = row0 + tid;
        if (rr > count - 1) rr = count - 1;
        reinterpret_cast<int*>(smem + SLIST)[tid] = g_list[region][rr];
        reinterpret_cast<float*>(smem + SROW)[tid] = 0.0f;
    }
    if (tid >= TM && tid < TM + TN) {
        int c = tid - TM;
        int cls = col0 + c;
        reinterpret_cast<float*>(smem + SBIAS)[c] =
            (cls < width) ? bias[lo + cls] : __int_as_float(0xff800000);  // -inf
    }
    __syncthreads();

    const int* listp = reinterpret_cast<const int*>(smem + SLIST);
    const int lane = tid & 31, wid = tid >> 5;
    const int sub = lane >> 3;               // row within 4-row group
    const int pos = lane & 7;                // 16B unit within 128B row

    // A: 4 ops/thread (16KB); B: 8 ops/thread (32KB) — R8's exact mappings
    uint32_t aoff[4], soffA[4];
#pragma unroll
    for (int j = 0; j < 4; j++) {
        int r = wid * 16 + j * 4 + sub;      // 0..127
        aoff[j] = (uint32_t)listp[r] * DIN + pos * 8;
        soffA[j] = SW((uint32_t)(r * 128 + pos * 16));
    }
    uint32_t boff[8], soffB[8];
#pragma unroll
    for (int j = 0; j < 8; j++) {
        int r = wid * 32 + j * 4 + sub;      // 0..255
        int cls = col0 + r;
        boff[j] = (uint32_t)(lo + ((cls < width) ? cls : width - 1)) * DIN + pos * 8;
        soffB[j] = SW((uint32_t)(r * 128 + pos * 16));
    }

    const int wm = wid & 1, wn = wid >> 1;

    float acc[4][8][4];
#pragma unroll
    for (int mi = 0; mi < 4; mi++)
#pragma unroll
        for (int nj = 0; nj < 8; nj++)
#pragma unroll
            for (int e = 0; e < 4; e++) acc[mi][nj][e] = 0.0f;

#pragma unroll
    for (int j = 0; j < 4; j++) cp_async16(sb + SA(0) + soffA[j], g_hbf + aoff[j]);
#pragma unroll
    for (int j = 0; j < 8; j++) cp_async16(sb + SB(0) + soffB[j], g_wbf + boff[j]);
    CP_COMMIT();

    for (int kc = 0; kc < NKC; kc++) {
        const int cur = kc & 1;
        if (kc + 1 < NKC) {
            const int nxt = cur ^ 1;
            const uint32_t kadd = (uint32_t)(kc + 1) * KC;
#pragma unroll
            for (int j = 0; j < 4; j++)
                cp_async16(sb + SA(nxt) + soffA[j], g_hbf + aoff[j] + kadd);
#pragma unroll
            for (int j = 0; j < 8; j++)
                cp_async16(sb + SB(nxt) + soffB[j], g_wbf + boff[j] + kadd);
            CP_COMMIT();
            CP_WAIT(1);
        } else {
            CP_WAIT(0);
        }
        __syncthreads();
#pragma unroll
        for (int ks = 0; ks < 4; ks++) {
            uint32_t af[4][4];
#pragma unroll
            for (int mi = 0; mi < 4; mi++) {
                int r  = wm * 64 + mi * 16 + (lane & 15);
                int kb = ks * 16 + ((lane >> 4) << 3);
                lds_frag4(af[mi], sb + SA(cur) + SW((uint32_t)(r * 128 + kb * 2)));
            }
            uint32_t bf[4][4];
#pragma unroll
            for (int np = 0; np < 4; np++) {
                int cl = wn * 64 + np * 16 + (lane & 7) + ((lane & 16) ? 8 : 0);
                int kb = ks * 16 + ((lane & 8) ? 8 : 0);
                lds_frag4(bf[np], sb + SB(cur) + SW((uint32_t)(cl * 128 + kb * 2)));
            }
#pragma unroll
            for (int mi = 0; mi < 4; mi++)
#pragma unroll
                for (int nj = 0; nj < 8; nj++)
                    mma16816(acc[mi][nj], af[mi],
                             bf[nj >> 1][(nj & 1) * 2], bf[nj >> 1][(nj & 1) * 2 + 1]);
        }
        __syncthreads();
    }

    epilogue(smem, acc, wm, wn, lane, tid, region, row0, count, listp);
}

// ---------------- kernel 3: finalize NLL ----------------
__global__ void finalize_kernel(float* __restrict__ out) {
    int t = blockIdx.x * blockDim.x + threadIdx.x;
    if (t >= NTOK) return;
    int r = g_cid[t];
    float ch = __expf(g_clogit[t][0]) + __expf(g_clogit[t][1]) + __expf(g_clogit[t][2]);
    float lse_head = __logf(g_S[0][t] + ch);
    float nll;
    if (r == 0) {
        nll = lse_head - g_tlogit[t];
    } else {
        float lse_tail = __logf(g_S[r][t]);
        // reference: head_logprob[:, -i] for region i -> cluster column (3 - i)
        nll = lse_head + lse_tail - g_clogit[t][3 - r] - g_tlogit[t];
    }
    out[t] = nll;
}

// ---------------- launcher ----------------
extern "C" void kernel_launch(void* const* d_in, const int* in_sizes, int n_in,
                              void* d_out, int out_size) {
    const float* hidden = (const float*)d_in[0];
    const int*   target = (const int*)d_in[1];
    const float* weight = (const float*)d_in[2];
    const float* bias   = (const float*)d_in[3];
    const float* cw     = (const float*)d_in[4];
    const float* cb     = (const float*)d_in[5];
    float* out = (float*)d_out;

    cudaFuncSetAttribute(gemm_sumexp,
                         cudaFuncAttributeMaxDynamicSharedMemorySize, SMEM_TOTAL);
    cudaFuncSetAttribute(conv_gemm_sumexp,
                         cudaFuncAttributeMaxDynamicSharedMemorySize, SMEM_TOTAL);

    zero_kernel<<<1, 256>>>();
    prep_kernel<<<128, 256>>>(hidden, target, weight, bias, cw, cb);

    // bf16 hidden (tiny)
    __nv_bfloat16* d_hbf = nullptr; cudaGetSymbolAddress((void**)&d_hbf, g_hbf);
    const size_t h8 = (size_t)NTOK * DIN / 8;
    convert_kernel<<<(unsigned)((h8 + 255) / 256), 256>>>(hidden, d_hbf, h8);

    // M-tile 0 GEMM fused with weight convert (writes g_wbf), then M-tiles 1..7
    conv_gemm_sumexp<<<dim3(1, NT_TOTAL), GT, SMEM_TOTAL>>>(weight, bias);
    gemm_sumexp<<<dim3(7, NT_TOTAL), GT, SMEM_TOTAL>>>(bias);

    finalize_kernel<<<4, 256>>>(out);
}

// round 14
// speedup vs baseline: 1.2290x; 1.0615x over previous
#include <cuda_runtime.h>
#include <cuda_bf16.h>
#include <cstdint>

// ---------------- problem constants ----------------
#define NTOK 1024
#define DIN  1024
#define NCLS 267735
#define WELEMS ((size_t)NCLS * DIN)          // 274,160,640
// regions: [0,20000) head, [20000,40000), [40000,200000), [200000,267735)

// ---------------- GEMM tile config ----------------
#define TM 128
#define TN 256
#define KC 64
#define NKC 16              // DIN / KC
#define GT 256              // 8 warps: 2 M-warps x 4 N-warps, warp tile 64x64

// N-tile counts per region (classes / TN, ceil)
#define NT0 79
#define NT1 79
#define NT2 625
#define NT3 265
#define NT_TOTAL (NT0 + NT1 + NT2 + NT3)   // 1048

// smem byte offsets. A: 2 x 16KB, B: 2 x 32KB (bf16, 128B rows, SW128)
#define SA(buf) ((buf) * 16384)
#define SB(buf) (32768 + (buf) * 32768)
#define SBIAS 98304                          // 256 f32
#define SLIST 99328                          // 128 int
#define SROW  99840                          // 128 f32
#define SMEM_TOTAL 100352

#define SW(o) ((o) ^ (((o) >> 3) & 0x70))    // SW128 swizzle on byte offsets

// ---------------- device scratch (static; no allocation) ----------------
__device__ __nv_bfloat16 g_wbf[WELEMS];      // bf16 weight (548 MB), written by conv_gemm
__device__ __nv_bfloat16 g_hbf[NTOK * DIN];  // bf16 hidden
__device__ float g_S[4][NTOK];
__device__ int   g_list[4][NTOK];
__device__ int   g_count[4];
__device__ float g_tlogit[NTOK];
__device__ float g_clogit[NTOK][3];
__device__ int   g_cid[NTOK];

// ---------------- small helpers ----------------
__device__ __forceinline__ uint32_t smem_u32(const void* p) {
    uint32_t a;
    asm("{ .reg .u64 t; cvta.to.shared.u64 t, %1; cvt.u32.u64 %0, t; }" : "=r"(a) : "l"(p));
    return a;
}
__device__ __forceinline__ uint32_t pack_bf16(float lo, float hi) {
    __nv_bfloat162 h = __floats2bfloat162_rn(lo, hi);
    return *reinterpret_cast<uint32_t*>(&h);
}
__device__ __forceinline__ void cp_async16(uint32_t saddr, const void* gaddr) {
    asm volatile("cp.async.cg.shared.global [%0], [%1], 16;" :: "r"(saddr), "l"(gaddr));
}
#define CP_COMMIT() asm volatile("cp.async.commit_group;" ::: "memory")
#define CP_WAIT(n)  asm volatile("cp.async.wait_group %0;" :: "n"(n) : "memory")
__device__ __forceinline__ void prefetch_l2(const void* gaddr) {
    asm volatile("prefetch.global.L2 [%0];" :: "l"(gaddr));
}
__device__ __forceinline__ void lds_frag4(uint32_t r[4], uint32_t addr) {
    asm volatile("ldmatrix.sync.aligned.m8n8.x4.shared.b16 {%0,%1,%2,%3}, [%4];"
        : "=r"(r[0]), "=r"(r[1]), "=r"(r[2]), "=r"(r[3]) : "r"(addr));
}
__device__ __forceinline__ void sts64(uint32_t addr, uint2 v) {
    asm volatile("st.shared.v2.u32 [%0], {%1,%2};" :: "r"(addr), "r"(v.x), "r"(v.y) : "memory");
}
__device__ __forceinline__ void mma16816(float d[4], const uint32_t a[4],
                                         uint32_t b0, uint32_t b1) {
    asm volatile("mma.sync.aligned.m16n8k16.row.col.f32.bf16.bf16.f32 "
        "{%0,%1,%2,%3}, {%4,%5,%6,%7}, {%8,%9}, {%0,%1,%2,%3};"
        : "+f"(d[0]), "+f"(d[1]), "+f"(d[2]), "+f"(d[3])
        : "r"(a[0]), "r"(a[1]), "r"(a[2]), "r"(a[3]), "r"(b0), "r"(b1));
}

// region mapping from concatenated N-tile index
__device__ __forceinline__ void region_map(int nt_in, int& region, int& lo, int& width, int& nt) {
    nt = nt_in;
    if (nt < NT0)                  { region = 0; lo = 0;      width = 20000;  }
    else if (nt < NT0 + NT1)       { region = 1; lo = 20000;  width = 20000;  nt -= NT0; }
    else if (nt < NT0 + NT1 + NT2) { region = 2; lo = 40000;  width = 160000; nt -= NT0 + NT1; }
    else                           { region = 3; lo = 200000; width = 67735;  nt -= NT0 + NT1 + NT2; }
}

// ---------------- kernel 0: reset scratch ----------------
__global__ void zero_kernel() {
    int t = threadIdx.x;
    for (int i = t; i < 4 * NTOK; i += blockDim.x) (&g_S[0][0])[i] = 0.0f;
    for (int i = t; i < NTOK; i += blockDim.x) g_list[0][i] = i;
    if (t == 0) g_count[0] = NTOK;
    if (t >= 1 && t < 4) g_count[t] = 0;
}

// ---------------- f32 -> bf16 streaming convert (hidden; 8 elems / thread) ----------------
__global__ void convert_kernel(const float* __restrict__ src,
                               __nv_bfloat16* __restrict__ dst, size_t n8) {
    size_t i = (size_t)blockIdx.x * blockDim.x + threadIdx.x;
    if (i >= n8) return;
    const float4* p = reinterpret_cast<const float4*>(src) + i * 2;
    float4 a = p[0], b = p[1];
    uint4 o;
    o.x = pack_bf16(a.x, a.y); o.y = pack_bf16(a.z, a.w);
    o.z = pack_bf16(b.x, b.y); o.w = pack_bf16(b.z, b.w);
    reinterpret_cast<uint4*>(dst)[i] = o;
}

// ---------------- kernel 1: per-token prep (exact f32 dots + compaction) ----------------
__global__ void prep_kernel(const float* __restrict__ hidden,
                            const int* __restrict__ target,   // int32 (JAX x64 disabled)
                            const float* __restrict__ weight,
                            const float* __restrict__ bias,
                            const float* __restrict__ cw,
                            const float* __restrict__ cb) {
    int gw = (int)((blockIdx.x * blockDim.x + threadIdx.x) >> 5);
    int lane = threadIdx.x & 31;
    if (gw >= NTOK) return;
    const int t = target[gw];
    const float4* h4  = reinterpret_cast<const float4*>(hidden + (size_t)gw * DIN);
    const float4* w4  = reinterpret_cast<const float4*>(weight + (size_t)t * DIN);
    const float4* c40 = reinterpret_cast<const float4*>(cw);
    const float4* c41 = reinterpret_cast<const float4*>(cw + DIN);
    const float4* c42 = reinterpret_cast<const float4*>(cw + 2 * DIN);
    float at = 0.f, a0 = 0.f, a1 = 0.f, a2 = 0.f;
#pragma unroll
    for (int j = 0; j < 8; j++) {
        int i = lane + 32 * j;
        float4 h = h4[i];
        float4 w = w4[i];
        at += h.x * w.x + h.y * w.y + h.z * w.z + h.w * w.w;
        float4 q = c40[i]; a0 += h.x * q.x + h.y * q.y + h.z * q.z + h.w * q.w;
        q = c41[i];        a1 += h.x * q.x + h.y * q.y + h.z * q.z + h.w * q.w;
        q = c42[i];        a2 += h.x * q.x + h.y * q.y + h.z * q.z + h.w * q.w;
    }
#pragma unroll
    for (int o = 16; o > 0; o >>= 1) {
        at += __shfl_xor_sync(0xffffffffu, at, o);
        a0 += __shfl_xor_sync(0xffffffffu, a0, o);
        a1 += __shfl_xor_sync(0xffffffffu, a1, o);
        a2 += __shfl_xor_sync(0xffffffffu, a2, o);
    }
    if (lane == 0) {
        g_tlogit[gw] = at + bias[t];
        g_clogit[gw][0] = a0 + cb[0];
        g_clogit[gw][1] = a1 + cb[1];
        g_clogit[gw][2] = a2 + cb[2];
        int r = (t < 20000) ? 0 : (t < 40000) ? 1 : (t < 200000) ? 2 : 3;
        g_cid[gw] = r;
        if (r > 0) {
            int idx = atomicAdd(&g_count[r], 1);
            g_list[r][idx] = gw;
        }
    }
}

// ---------------- shared epilogue ----------------
__device__ __forceinline__ void epilogue(char* smem, float acc[4][8][4],
                                         int wm, int wn, int lane, int tid,
                                         int region, int row0, int count,
                                         const int* listp) {
    const float* bs = reinterpret_cast<const float*>(smem + SBIAS);
    float* rowsum = reinterpret_cast<float*>(smem + SROW);
    float loc[8];
#pragma unroll
    for (int i = 0; i < 8; i++) loc[i] = 0.0f;
#pragma unroll
    for (int mi = 0; mi < 4; mi++) {
#pragma unroll
        for (int nj = 0; nj < 8; nj++) {
            int c = wn * 64 + nj * 8 + 2 * (lane & 3);
            float b0 = bs[c], b1 = bs[c + 1];
            loc[2*mi]   += __expf(acc[mi][nj][0] + b0) + __expf(acc[mi][nj][1] + b1);
            loc[2*mi+1] += __expf(acc[mi][nj][2] + b0) + __expf(acc[mi][nj][3] + b1);
        }
    }
#pragma unroll
    for (int i = 0; i < 8; i++) {
        loc[i] += __shfl_xor_sync(0xffffffffu, loc[i], 1);
        loc[i] += __shfl_xor_sync(0xffffffffu, loc[i], 2);
    }
    if ((lane & 3) == 0) {
        int g = lane >> 2;
#pragma unroll
        for (int mi = 0; mi < 4; mi++) {
            atomicAdd(&rowsum[wm * 64 + mi * 16 + g],     loc[2*mi]);
            atomicAdd(&rowsum[wm * 64 + mi * 16 + g + 8], loc[2*mi+1]);
        }
    }
    __syncthreads();
    if (tid < TM && row0 + tid < count)
        atomicAdd(&g_S[region][listp[tid]], rowsum[tid]);
}

// ---------------- kernel 2a: M-tile-0 GEMM fused with weight f32->bf16 convert ----------------
// B tile staged by LDG.128 f32 -> cvt -> STS bf16; bf16 also written back to g_wbf.
// L2 prefetch of chunk kc+1 keeps DRAM busy during the mma phase.
__global__ __launch_bounds__(GT, 1)
void conv_gemm_sumexp(const float* __restrict__ weight,
                      const float* __restrict__ bias) {
    extern __shared__ char smem[];
    const int tid = threadIdx.x;
    int region, lo, width, nt;
    region_map(blockIdx.y, region, lo, width, nt);
    const int count = g_count[region];
    const int row0 = 0;
    const int col0 = nt * TN;
    const uint32_t sb = smem_u32(smem);

    if (tid < TM) {
        int rr = tid;
        if (rr > count - 1) rr = count - 1;
        reinterpret_cast<int*>(smem + SLIST)[tid] = g_list[region][rr];
        reinterpret_cast<float*>(smem + SROW)[tid] = 0.0f;
    }
    {   // bias tile: one entry per thread (TN == GT == 256)
        int cls = col0 + tid;
        reinterpret_cast<float*>(smem + SBIAS)[tid] =
            (cls < width) ? bias[lo + cls] : __int_as_float(0xff800000);  // -inf
    }
    __syncthreads();

    const int* listp = reinterpret_cast<const int*>(smem + SLIST);
    const int lane = tid & 31, wid = tid >> 5;

    // A (bf16) cp.async mapping — 4 ops/thread: full 16KB tile coverage
    const int sub = lane >> 3;               // row within 4-row group
    const int pos = lane & 7;                // 16B unit within 128B row
    uint32_t aoff[4], soffA[4];
#pragma unroll
    for (int j = 0; j < 4; j++) {
        int r = wid * 16 + j * 4 + sub;      // 0..127
        aoff[j] = (uint32_t)listp[r] * DIN + pos * 8;
        soffA[j] = SW((uint32_t)(r * 128 + pos * 16));
    }

    // B staging mapping: row = o*16 + (tid>>4); ucol = tid&15 (4 f32 elems per op)
    const int rhi = tid >> 4, ucol = tid & 15;
    uint32_t goff[16], sboff[16];
#pragma unroll
    for (int o = 0; o < 16; o++) {
        int row = o * 16 + rhi;              // 0..255
        int cls = col0 + row;
        if (cls >= width) cls = width - 1;   // clamp (dup writes of same data: benign)
        goff[o] = (uint32_t)(lo + cls) * DIN + ucol * 4;    // element offset (f32 & bf16)
        sboff[o] = SW((uint32_t)(row * 128 + ucol * 8));
    }

    const int wm = wid & 1, wn = wid >> 1;

    float acc[4][8][4];
#pragma unroll
    for (int mi = 0; mi < 4; mi++)
#pragma unroll
        for (int nj = 0; nj < 8; nj++)
#pragma unroll
            for (int e = 0; e < 4; e++) acc[mi][nj][e] = 0.0f;

    for (int kc = 0; kc < NKC; kc++) {
        const uint32_t kadd = (uint32_t)kc * KC;
        // A async into buffer 0
#pragma unroll
        for (int j = 0; j < 4; j++)
            cp_async16(sb + SA(0) + soffA[j], g_hbf + aoff[j] + kadd);
        CP_COMMIT();
        // B: two bursts of 8 x (LDG.128 f32 -> cvt -> STS.64 + STG.64 writeback)
#pragma unroll
        for (int h = 0; h < 2; h++) {
            float4 v[8];
#pragma unroll
            for (int j = 0; j < 8; j++)
                v[j] = *reinterpret_cast<const float4*>(weight + goff[h * 8 + j] + kadd);
#pragma unroll
            for (int j = 0; j < 8; j++) {
                uint2 p;
                p.x = pack_bf16(v[j].x, v[j].y);
                p.y = pack_bf16(v[j].z, v[j].w);
                sts64(sb + SB(0) + sboff[h * 8 + j], p);
                *reinterpret_cast<uint2*>(g_wbf + goff[h * 8 + j] + kadd) = p;
            }
        }
        // L2 prefetch of next chunk's f32 weight — overlaps DRAM with mma phase
        if (kc + 1 < NKC) {
            const uint32_t knext = kadd + KC;
#pragma unroll
            for (int o = 0; o < 16; o++)
                prefetch_l2(weight + goff[o] + knext);
        }
        CP_WAIT(0);
        __syncthreads();
#pragma unroll
        for (int ks = 0; ks < 4; ks++) {
            uint32_t afr[4][4];
#pragma unroll
            for (int mi = 0; mi < 4; mi++) {
                int r  = wm * 64 + mi * 16 + (lane & 15);
                int kb = ks * 16 + ((lane >> 4) << 3);
                lds_frag4(afr[mi], sb + SA(0) + SW((uint32_t)(r * 128 + kb * 2)));
            }
            uint32_t bfr[4][4];
#pragma unroll
            for (int np = 0; np < 4; np++) {
                int cl = wn * 64 + np * 16 + (lane & 7) + ((lane & 16) ? 8 : 0);
                int kb = ks * 16 + ((lane & 8) ? 8 : 0);
                lds_frag4(bfr[np], sb + SB(0) + SW((uint32_t)(cl * 128 + kb * 2)));
            }
#pragma unroll
            for (int mi = 0; mi < 4; mi++)
#pragma unroll
                for (int nj = 0; nj < 8; nj++)
                    mma16816(acc[mi][nj], afr[mi],
                             bfr[nj >> 1][(nj & 1) * 2], bfr[nj >> 1][(nj & 1) * 2 + 1]);
        }
        __syncthreads();
    }

    epilogue(smem, acc, wm, wn, lane, tid, region, row0, count, listp);
}

// ---------------- kernel 2b: M-tiles 1..7 GEMM (bf16 cp.async, R8 path) ----------------
__global__ __launch_bounds__(GT, 1)
void gemm_sumexp(const float* __restrict__ bias) {
    extern __shared__ char smem[];
    const int tid = threadIdx.x;
    int region, lo, width, nt;
    region_map(blockIdx.y, region, lo, width, nt);
    const int count = g_count[region];
    const int row0 = (blockIdx.x + 1) * TM;  // M-tiles 1..7
    if (row0 >= count) return;
    const int col0 = nt * TN;
    const uint32_t sb = smem_u32(smem);

    if (tid < TM) {
        int rr = row0 + tid;
        if (rr > count - 1) rr = count - 1;
        reinterpret_cast<int*>(smem + SLIST)[tid] = g_list[region][rr];
        reinterpret_cast<float*>(smem + SROW)[tid] = 0.0f;
    }
    {   // bias tile: one entry per thread (TN == GT == 256)
        int cls = col0 + tid;
        reinterpret_cast<float*>(smem + SBIAS)[tid] =
            (cls < width) ? bias[lo + cls] : __int_as_float(0xff800000);  // -inf
    }
    __syncthreads();

    const int* listp = reinterpret_cast<const int*>(smem + SLIST);
    const int lane = tid & 31, wid = tid >> 5;
    const int sub = lane >> 3;               // row within 4-row group
    const int pos = lane & 7;                // 16B unit within 128B row

    // A: 4 ops/thread (16KB); B: 8 ops/thread (32KB)
    uint32_t aoff[4], soffA[4];
#pragma unroll
    for (int j = 0; j < 4; j++) {
        int r = wid * 16 + j * 4 + sub;      // 0..127
        aoff[j] = (uint32_t)listp[r] * DIN + pos * 8;
        soffA[j] = SW((uint32_t)(r * 128 + pos * 16));
    }
    uint32_t boff[8], soffB[8];
#pragma unroll
    for (int j = 0; j < 8; j++) {
        int r = wid * 32 + j * 4 + sub;      // 0..255
        int cls = col0 + r;
        boff[j] = (uint32_t)(lo + ((cls < width) ? cls : width - 1)) * DIN + pos * 8;
        soffB[j] = SW((uint32_t)(r * 128 + pos * 16));
    }

    const int wm = wid & 1, wn = wid >> 1;

    float acc[4][8][4];
#pragma unroll
    for (int mi = 0; mi < 4; mi++)
#pragma unroll
        for (int nj = 0; nj < 8; nj++)
#pragma unroll
            for (int e = 0; e < 4; e++) acc[mi][nj][e] = 0.0f;

#pragma unroll
    for (int j = 0; j < 4; j++) cp_async16(sb + SA(0) + soffA[j], g_hbf + aoff[j]);
#pragma unroll
    for (int j = 0; j < 8; j++) cp_async16(sb + SB(0) + soffB[j], g_wbf + boff[j]);
    CP_COMMIT();

    for (int kc = 0; kc < NKC; kc++) {
        const int cur = kc & 1;
        if (kc + 1 < NKC) {
            const int nxt = cur ^ 1;
            const uint32_t kadd = (uint32_t)(kc + 1) * KC;
#pragma unroll
            for (int j = 0; j < 4; j++)
                cp_async16(sb + SA(nxt) + soffA[j], g_hbf + aoff[j] + kadd);
#pragma unroll
            for (int j = 0; j < 8; j++)
                cp_async16(sb + SB(nxt) + soffB[j], g_wbf + boff[j] + kadd);
            CP_COMMIT();
            CP_WAIT(1);
        } else {
            CP_WAIT(0);
        }
        __syncthreads();
#pragma unroll
        for (int ks = 0; ks < 4; ks++) {
            uint32_t af[4][4];
#pragma unroll
            for (int mi = 0; mi < 4; mi++) {
                int r  = wm * 64 + mi * 16 + (lane & 15);
                int kb = ks * 16 + ((lane >> 4) << 3);
                lds_frag4(af[mi], sb + SA(cur) + SW((uint32_t)(r * 128 + kb * 2)));
            }
            uint32_t bf[4][4];
#pragma unroll
            for (int np = 0; np < 4; np++) {
                int cl = wn * 64 + np * 16 + (lane & 7) + ((lane & 16) ? 8 : 0);
                int kb = ks * 16 + ((lane & 8) ? 8 : 0);
                lds_frag4(bf[np], sb + SB(cur) + SW((uint32_t)(cl * 128 + kb * 2)));
            }
#pragma unroll
            for (int mi = 0; mi < 4; mi++)
#pragma unroll
                for (int nj = 0; nj < 8; nj++)
                    mma16816(acc[mi][nj], af[mi],
                             bf[nj >> 1][(nj & 1) * 2], bf[nj >> 1][(nj & 1) * 2 + 1]);
        }
        __syncthreads();
    }

    epilogue(smem, acc, wm, wn, lane, tid, region, row0, count, listp);
}

// ---------------- kernel 3: finalize NLL ----------------
__global__ void finalize_kernel(float* __restrict__ out) {
    int t = blockIdx.x * blockDim.x + threadIdx.x;
    if (t >= NTOK) return;
    int r = g_cid[t];
    float ch = __expf(g_clogit[t][0]) + __expf(g_clogit[t][1]) + __expf(g_clogit[t][2]);
    float lse_head = __logf(g_S[0][t] + ch);
    float nll;
    if (r == 0) {
        nll = lse_head - g_tlogit[t];
    } else {
        float lse_tail = __logf(g_S[r][t]);
        // reference: head_logprob[:, -i] for region i -> cluster column (3 - i)
        nll = lse_head + lse_tail - g_clogit[t][3 - r] - g_tlogit[t];
    }
    out[t] = nll;
}

// ---------------- launcher ----------------
extern "C" void kernel_launch(void* const* d_in, const int* in_sizes, int n_in,
                              void* d_out, int out_size) {
    const float* hidden = (const float*)d_in[0];
    const int*   target = (const int*)d_in[1];
    const float* weight = (const float*)d_in[2];
    const float* bias   = (const float*)d_in[3];
    const float* cw     = (const float*)d_in[4];
    const float* cb     = (const float*)d_in[5];
    float* out = (float*)d_out;

    cudaFuncSetAttribute(gemm_sumexp,
                         cudaFuncAttributeMaxDynamicSharedMemorySize, SMEM_TOTAL);
    cudaFuncSetAttribute(conv_gemm_sumexp,
                         cudaFuncAttributeMaxDynamicSharedMemorySize, SMEM_TOTAL);

    zero_kernel<<<1, 256>>>();
    prep_kernel<<<128, 256>>>(hidden, target, weight, bias, cw, cb);

    // bf16 hidden (tiny)
    __nv_bfloat16* d_hbf = nullptr; cudaGetSymbolAddress((void**)&d_hbf, g_hbf);
    const size_t h8 = (size_t)NTOK * DIN / 8;
    convert_kernel<<<(unsigned)((h8 + 255) / 256), 256>>>(hidden, d_hbf, h8);

    // M-tile 0 GEMM fused with weight convert (writes g_wbf), then M-tiles 1..7
    conv_gemm_sumexp<<<dim3(1, NT_TOTAL), GT, SMEM_TOTAL>>>(weight, bias);
    gemm_sumexp<<<dim3(7, NT_TOTAL), GT, SMEM_TOTAL>>>(bias);

    finalize_kernel<<<4, 256>>>(out);
}

// round 17
// speedup vs baseline: 1.2392x; 1.0082x over previous
#include <cuda_runtime.h>
#include <cuda_bf16.h>
#include <cstdint>

// ---------------- problem constants ----------------
#define NTOK 1024
#define DIN  1024
#define NCLS 267735
#define WELEMS ((size_t)NCLS * DIN)          // 274,160,640
// regions: [0,20000) head, [20000,40000), [40000,200000), [200000,267735)

// ---------------- GEMM tile config ----------------
#define TM 128
#define TN 256
#define KC 64
#define NKC 16              // DIN / KC
#define GT 256              // 8 warps: 2 M-warps x 4 N-warps, warp tile 64x64
#define NSTAGE 4            // launch-B pipeline depth

// N-tile counts per region (classes / TN, ceil)
#define NT0 79
#define NT1 79
#define NT2 625
#define NT3 265
#define NT_TOTAL (NT0 + NT1 + NT2 + NT3)   // 1048

#define SW(o) ((o) ^ (((o) >> 3) & 0x70))    // SW128 swizzle on byte offsets

// ---- launch-B smem layout: 4 stages x (A 16KB + B 32KB) ----
#define BSA(s) ((s) * 16384)                 // 0..65536
#define BSB(s) (65536 + (s) * 32768)         // ..196608
#define BBIAS 196608                         // 256 f32
#define BLIST 197632                         // 128 int
#define BROW  198144                         // 128 f32
#define BSMEM 198656

// ---- conv kernel smem layout: single stage ----
#define CSA 0                                // A bf16 16KB
#define CSB 16384                            // B bf16 32KB
#define CBIAS 49152
#define CLIST 50176
#define CROW  50688
#define CSMEM 51200

// ---------------- device scratch (static; no allocation) ----------------
__device__ __nv_bfloat16 g_wbf[WELEMS];      // bf16 weight (548 MB), written by conv_gemm
__device__ __nv_bfloat16 g_hbf[NTOK * DIN];  // bf16 hidden
__device__ float g_S[4][NTOK];
__device__ int   g_list[4][NTOK];
__device__ int   g_count[4];
__device__ float g_tlogit[NTOK];
__device__ float g_clogit[NTOK][3];
__device__ int   g_cid[NTOK];

// ---------------- small helpers ----------------
__device__ __forceinline__ uint32_t smem_u32(const void* p) {
    uint32_t a;
    asm("{ .reg .u64 t; cvta.to.shared.u64 t, %1; cvt.u32.u64 %0, t; }" : "=r"(a) : "l"(p));
    return a;
}
__device__ __forceinline__ uint32_t pack_bf16(float lo, float hi) {
    __nv_bfloat162 h = __floats2bfloat162_rn(lo, hi);
    return *reinterpret_cast<uint32_t*>(&h);
}
__device__ __forceinline__ void cp_async16(uint32_t saddr, const void* gaddr) {
    asm volatile("cp.async.cg.shared.global [%0], [%1], 16;" :: "r"(saddr), "l"(gaddr));
}
#define CP_COMMIT() asm volatile("cp.async.commit_group;" ::: "memory")
#define CP_WAIT(n)  asm volatile("cp.async.wait_group %0;" :: "n"(n) : "memory")
__device__ __forceinline__ void prefetch_l2(const void* gaddr) {
    asm volatile("prefetch.global.L2 [%0];" :: "l"(gaddr));
}
__device__ __forceinline__ void lds_frag4(uint32_t r[4], uint32_t addr) {
    asm volatile("ldmatrix.sync.aligned.m8n8.x4.shared.b16 {%0,%1,%2,%3}, [%4];"
        : "=r"(r[0]), "=r"(r[1]), "=r"(r[2]), "=r"(r[3]) : "r"(addr));
}
__device__ __forceinline__ void sts64(uint32_t addr, uint2 v) {
    asm volatile("st.shared.v2.u32 [%0], {%1,%2};" :: "r"(addr), "r"(v.x), "r"(v.y) : "memory");
}
__device__ __forceinline__ void mma16816(float d[4], const uint32_t a[4],
                                         uint32_t b0, uint32_t b1) {
    asm volatile("mma.sync.aligned.m16n8k16.row.col.f32.bf16.bf16.f32 "
        "{%0,%1,%2,%3}, {%4,%5,%6,%7}, {%8,%9}, {%0,%1,%2,%3};"
        : "+f"(d[0]), "+f"(d[1]), "+f"(d[2]), "+f"(d[3])
        : "r"(a[0]), "r"(a[1]), "r"(a[2]), "r"(a[3]), "r"(b0), "r"(b1));
}

// region mapping from concatenated N-tile index
__device__ __forceinline__ void region_map(int nt_in, int& region, int& lo, int& width, int& nt) {
    nt = nt_in;
    if (nt < NT0)                  { region = 0; lo = 0;      width = 20000;  }
    else if (nt < NT0 + NT1)       { region = 1; lo = 20000;  width = 20000;  nt -= NT0; }
    else if (nt < NT0 + NT1 + NT2) { region = 2; lo = 40000;  width = 160000; nt -= NT0 + NT1; }
    else                           { region = 3; lo = 200000; width = 67735;  nt -= NT0 + NT1 + NT2; }
}

// ---------------- kernel 0: reset scratch ----------------
__global__ void zero_kernel() {
    int t = threadIdx.x;
    for (int i = t; i < 4 * NTOK; i += blockDim.x) (&g_S[0][0])[i] = 0.0f;
    for (int i = t; i < NTOK; i += blockDim.x) g_list[0][i] = i;
    if (t == 0) g_count[0] = NTOK;
    if (t >= 1 && t < 4) g_count[t] = 0;
}

// ---------------- f32 -> bf16 streaming convert (hidden; 8 elems / thread) ----------------
__global__ void convert_kernel(const float* __restrict__ src,
                               __nv_bfloat16* __restrict__ dst, size_t n8) {
    size_t i = (size_t)blockIdx.x * blockDim.x + threadIdx.x;
    if (i >= n8) return;
    const float4* p = reinterpret_cast<const float4*>(src) + i * 2;
    float4 a = p[0], b = p[1];
    uint4 o;
    o.x = pack_bf16(a.x, a.y); o.y = pack_bf16(a.z, a.w);
    o.z = pack_bf16(b.x, b.y); o.w = pack_bf16(b.z, b.w);
    reinterpret_cast<uint4*>(dst)[i] = o;
}

// ---------------- kernel 1: per-token prep (exact f32 dots + compaction) ----------------
__global__ void prep_kernel(const float* __restrict__ hidden,
                            const int* __restrict__ target,   // int32 (JAX x64 disabled)
                            const float* __restrict__ weight,
                            const float* __restrict__ bias,
                            const float* __restrict__ cw,
                            const float* __restrict__ cb) {
    int gw = (int)((blockIdx.x * blockDim.x + threadIdx.x) >> 5);
    int lane = threadIdx.x & 31;
    if (gw >= NTOK) return;
    const int t = target[gw];
    const float4* h4  = reinterpret_cast<const float4*>(hidden + (size_t)gw * DIN);
    const float4* w4  = reinterpret_cast<const float4*>(weight + (size_t)t * DIN);
    const float4* c40 = reinterpret_cast<const float4*>(cw);
    const float4* c41 = reinterpret_cast<const float4*>(cw + DIN);
    const float4* c42 = reinterpret_cast<const float4*>(cw + 2 * DIN);
    float at = 0.f, a0 = 0.f, a1 = 0.f, a2 = 0.f;
#pragma unroll
    for (int j = 0; j < 8; j++) {
        int i = lane + 32 * j;
        float4 h = h4[i];
        float4 w = w4[i];
        at += h.x * w.x + h.y * w.y + h.z * w.z + h.w * w.w;
        float4 q = c40[i]; a0 += h.x * q.x + h.y * q.y + h.z * q.z + h.w * q.w;
        q = c41[i];        a1 += h.x * q.x + h.y * q.y + h.z * q.z + h.w * q.w;
        q = c42[i];        a2 += h.x * q.x + h.y * q.y + h.z * q.z + h.w * q.w;
    }
#pragma unroll
    for (int o = 16; o > 0; o >>= 1) {
        at += __shfl_xor_sync(0xffffffffu, at, o);
        a0 += __shfl_xor_sync(0xffffffffu, a0, o);
        a1 += __shfl_xor_sync(0xffffffffu, a1, o);
        a2 += __shfl_xor_sync(0xffffffffu, a2, o);
    }
    if (lane == 0) {
        g_tlogit[gw] = at + bias[t];
        g_clogit[gw][0] = a0 + cb[0];
        g_clogit[gw][1] = a1 + cb[1];
        g_clogit[gw][2] = a2 + cb[2];
        int r = (t < 20000) ? 0 : (t < 40000) ? 1 : (t < 200000) ? 2 : 3;
        g_cid[gw] = r;
        if (r > 0) {
            int idx = atomicAdd(&g_count[r], 1);
            g_list[r][idx] = gw;
        }
    }
}

// ---------------- shared epilogue (pointer-parameterized) ----------------
__device__ __forceinline__ void epilogue(const float* bs, float* rowsum,
                                         float acc[4][8][4],
                                         int wm, int wn, int lane, int tid,
                                         int region, int row0, int count,
                                         const int* listp) {
    float loc[8];
#pragma unroll
    for (int i = 0; i < 8; i++) loc[i] = 0.0f;
#pragma unroll
    for (int mi = 0; mi < 4; mi++) {
#pragma unroll
        for (int nj = 0; nj < 8; nj++) {
            int c = wn * 64 + nj * 8 + 2 * (lane & 3);
            float b0 = bs[c], b1 = bs[c + 1];
            loc[2*mi]   += __expf(acc[mi][nj][0] + b0) + __expf(acc[mi][nj][1] + b1);
            loc[2*mi+1] += __expf(acc[mi][nj][2] + b0) + __expf(acc[mi][nj][3] + b1);
        }
    }
#pragma unroll
    for (int i = 0; i < 8; i++) {
        loc[i] += __shfl_xor_sync(0xffffffffu, loc[i], 1);
        loc[i] += __shfl_xor_sync(0xffffffffu, loc[i], 2);
    }
    if ((lane & 3) == 0) {
        int g = lane >> 2;
#pragma unroll
        for (int mi = 0; mi < 4; mi++) {
            atomicAdd(&rowsum[wm * 64 + mi * 16 + g],     loc[2*mi]);
            atomicAdd(&rowsum[wm * 64 + mi * 16 + g + 8], loc[2*mi+1]);
        }
    }
    __syncthreads();
    if (tid < TM && row0 + tid < count)
        atomicAdd(&g_S[region][listp[tid]], rowsum[tid]);
}

// ---------------- kernel 2a: M-tile-0 GEMM fused with weight f32->bf16 convert ----------------
__global__ __launch_bounds__(GT, 1)
void conv_gemm_sumexp(const float* __restrict__ weight,
                      const float* __restrict__ bias) {
    extern __shared__ char smem[];
    const int tid = threadIdx.x;
    int region, lo, width, nt;
    region_map(blockIdx.y, region, lo, width, nt);
    const int count = g_count[region];
    const int row0 = 0;
    const int col0 = nt * TN;
    const uint32_t sb = smem_u32(smem);

    if (tid < TM) {
        int rr = tid;
        if (rr > count - 1) rr = count - 1;
        reinterpret_cast<int*>(smem + CLIST)[tid] = g_list[region][rr];
        reinterpret_cast<float*>(smem + CROW)[tid] = 0.0f;
    }
    {   // bias tile: one entry per thread (TN == GT == 256)
        int cls = col0 + tid;
        reinterpret_cast<float*>(smem + CBIAS)[tid] =
            (cls < width) ? bias[lo + cls] : __int_as_float(0xff800000);  // -inf
    }
    __syncthreads();

    const int* listp = reinterpret_cast<const int*>(smem + CLIST);
    const int lane = tid & 31, wid = tid >> 5;

    // A (bf16) cp.async mapping — 4 ops/thread: full 16KB tile coverage
    const int sub = lane >> 3;               // row within 4-row group
    const int pos = lane & 7;                // 16B unit within 128B row
    uint32_t aoff[4], soffA[4];
#pragma unroll
    for (int j = 0; j < 4; j++) {
        int r = wid * 16 + j * 4 + sub;      // 0..127
        aoff[j] = (uint32_t)listp[r] * DIN + pos * 8;
        soffA[j] = SW((uint32_t)(r * 128 + pos * 16));
    }

    // B staging mapping: row = o*16 + (tid>>4); ucol = tid&15 (4 f32 elems per op)
    const int rhi = tid >> 4, ucol = tid & 15;
    uint32_t goff[16], sboff[16];
#pragma unroll
    for (int o = 0; o < 16; o++) {
        int row = o * 16 + rhi;              // 0..255
        int cls = col0 + row;
        if (cls >= width) cls = width - 1;   // clamp (dup writes of same data: benign)
        goff[o] = (uint32_t)(lo + cls) * DIN + ucol * 4;    // element offset (f32 & bf16)
        sboff[o] = SW((uint32_t)(row * 128 + ucol * 8));
    }

    const int wm = wid & 1, wn = wid >> 1;

    float acc[4][8][4];
#pragma unroll
    for (int mi = 0; mi < 4; mi++)
#pragma unroll
        for (int nj = 0; nj < 8; nj++)
#pragma unroll
            for (int e = 0; e < 4; e++) acc[mi][nj][e] = 0.0f;

    for (int kc = 0; kc < NKC; kc++) {
        const uint32_t kadd = (uint32_t)kc * KC;
        // A async into the single stage
#pragma unroll
        for (int j = 0; j < 4; j++)
            cp_async16(sb + CSA + soffA[j], g_hbf + aoff[j] + kadd);
        CP_COMMIT();
        // B: two bursts of 8 x (LDG.128 f32 -> cvt -> STS.64 + STG.64 writeback)
#pragma unroll
        for (int h = 0; h < 2; h++) {
            float4 v[8];
#pragma unroll
            for (int j = 0; j < 8; j++)
                v[j] = *reinterpret_cast<const float4*>(weight + goff[h * 8 + j] + kadd);
#pragma unroll
            for (int j = 0; j < 8; j++) {
                uint2 p;
                p.x = pack_bf16(v[j].x, v[j].y);
                p.y = pack_bf16(v[j].z, v[j].w);
                sts64(sb + CSB + sboff[h * 8 + j], p);
                *reinterpret_cast<uint2*>(g_wbf + goff[h * 8 + j] + kadd) = p;
            }
        }
        // L2 prefetch of next chunk's f32 weight — overlaps DRAM with mma phase
        if (kc + 1 < NKC) {
            const uint32_t knext = kadd + KC;
#pragma unroll
            for (int o = 0; o < 16; o++)
                prefetch_l2(weight + goff[o] + knext);
        }
        CP_WAIT(0);
        __syncthreads();
#pragma unroll
        for (int ks = 0; ks < 4; ks++) {
            uint32_t afr[4][4];
#pragma unroll
            for (int mi = 0; mi < 4; mi++) {
                int r  = wm * 64 + mi * 16 + (lane & 15);
                int kb = ks * 16 + ((lane >> 4) << 3);
                lds_frag4(afr[mi], sb + CSA + SW((uint32_t)(r * 128 + kb * 2)));
            }
            uint32_t bfr[4][4];
#pragma unroll
            for (int np = 0; np < 4; np++) {
                int cl = wn * 64 + np * 16 + (lane & 7) + ((lane & 16) ? 8 : 0);
                int kb = ks * 16 + ((lane & 8) ? 8 : 0);
                lds_frag4(bfr[np], sb + CSB + SW((uint32_t)(cl * 128 + kb * 2)));
            }
#pragma unroll
            for (int mi = 0; mi < 4; mi++)
#pragma unroll
                for (int nj = 0; nj < 8; nj++)
                    mma16816(acc[mi][nj], afr[mi],
                             bfr[nj >> 1][(nj & 1) * 2], bfr[nj >> 1][(nj & 1) * 2 + 1]);
        }
        __syncthreads();
    }

    epilogue(reinterpret_cast<const float*>(smem + CBIAS),
             reinterpret_cast<float*>(smem + CROW),
             acc, wm, wn, lane, tid, region, row0, count, listp);
}

// ---------------- kernel 2b: M-tiles 1..7 GEMM (4-stage cp.async multistage) ----------------
__global__ __launch_bounds__(GT, 1)
void gemm_sumexp(const float* __restrict__ bias) {
    extern __shared__ char smem[];
    const int tid = threadIdx.x;
    int region, lo, width, nt;
    region_map(blockIdx.y, region, lo, width, nt);
    const int count = g_count[region];
    const int row0 = (blockIdx.x + 1) * TM;  // M-tiles 1..7
    if (row0 >= count) return;
    const int col0 = nt * TN;
    const uint32_t sb = smem_u32(smem);

    if (tid < TM) {
        int rr = row0 + tid;
        if (rr > count - 1) rr = count - 1;
        reinterpret_cast<int*>(smem + BLIST)[tid] = g_list[region][rr];
        reinterpret_cast<float*>(smem + BROW)[tid] = 0.0f;
    }
    {   // bias tile: one entry per thread (TN == GT == 256)
        int cls = col0 + tid;
        reinterpret_cast<float*>(smem + BBIAS)[tid] =
            (cls < width) ? bias[lo + cls] : __int_as_float(0xff800000);  // -inf
    }
    __syncthreads();

    const int* listp = reinterpret_cast<const int*>(smem + BLIST);
    const int lane = tid & 31, wid = tid >> 5;
    const int sub = lane >> 3;               // row within 4-row group
    const int pos = lane & 7;                // 16B unit within 128B row

    // A: 4 ops/thread (16KB); B: 8 ops/thread (32KB)
    uint32_t aoff[4], soffA[4];
#pragma unroll
    for (int j = 0; j < 4; j++) {
        int r = wid * 16 + j * 4 + sub;      // 0..127
        aoff[j] = (uint32_t)listp[r] * DIN + pos * 8;
        soffA[j] = SW((uint32_t)(r * 128 + pos * 16));
    }
    uint32_t boff[8], soffB[8];
#pragma unroll
    for (int j = 0; j < 8; j++) {
        int r = wid * 32 + j * 4 + sub;      // 0..255
        int cls = col0 + r;
        boff[j] = (uint32_t)(lo + ((cls < width) ? cls : width - 1)) * DIN + pos * 8;
        soffB[j] = SW((uint32_t)(r * 128 + pos * 16));
    }

    const int wm = wid & 1, wn = wid >> 1;

    float acc[4][8][4];
#pragma unroll
    for (int mi = 0; mi < 4; mi++)
#pragma unroll
        for (int nj = 0; nj < 8; nj++)
#pragma unroll
            for (int e = 0; e < 4; e++) acc[mi][nj][e] = 0.0f;

    // ---- prologue: issue stages 0..2 ----
#pragma unroll
    for (int s = 0; s < NSTAGE - 1; s++) {
        const uint32_t kadd = (uint32_t)s * KC;
#pragma unroll
        for (int j = 0; j < 4; j++)
            cp_async16(sb + BSA(s) + soffA[j], g_hbf + aoff[j] + kadd);
#pragma unroll
        for (int j = 0; j < 8; j++)
            cp_async16(sb + BSB(s) + soffB[j], g_wbf + boff[j] + kadd);
        CP_COMMIT();
    }

    for (int kc = 0; kc < NKC; kc++) {
        // wait until chunk kc has arrived: pending groups at this point = {kc..min(kc+2,15)}
        if (kc <= NKC - 3)      { CP_WAIT(2); }
        else if (kc == NKC - 2) { CP_WAIT(1); }
        else                    { CP_WAIT(0); }
        __syncthreads();        // data visible to all warps; all warps done reading stage (kc-1)
        if (kc + NSTAGE - 1 < NKC) {   // issue chunk kc+3 into the just-freed stage
            const int s = (kc + NSTAGE - 1) & (NSTAGE - 1);
            const uint32_t kadd = (uint32_t)(kc + NSTAGE - 1) * KC;
#pragma unroll
            for (int j = 0; j < 4; j++)
                cp_async16(sb + BSA(s) + soffA[j], g_hbf + aoff[j] + kadd);
#pragma unroll
            for (int j = 0; j < 8; j++)
                cp_async16(sb + BSB(s) + soffB[j], g_wbf + boff[j] + kadd);
            CP_COMMIT();
        }
        const int cur = kc & (NSTAGE - 1);
#pragma unroll
        for (int ks = 0; ks < 4; ks++) {
            uint32_t af[4][4];
#pragma unroll
            for (int mi = 0; mi < 4; mi++) {
                int r  = wm * 64 + mi * 16 + (lane & 15);
                int kb = ks * 16 + ((lane >> 4) << 3);
                lds_frag4(af[mi], sb + BSA(cur) + SW((uint32_t)(r * 128 + kb * 2)));
            }
            uint32_t bf[4][4];
#pragma unroll
            for (int np = 0; np < 4; np++) {
                int cl = wn * 64 + np * 16 + (lane & 7) + ((lane & 16) ? 8 : 0);
                int kb = ks * 16 + ((lane & 8) ? 8 : 0);
                lds_frag4(bf[np], sb + BSB(cur) + SW((uint32_t)(cl * 128 + kb * 2)));
            }
#pragma unroll
            for (int mi = 0; mi < 4; mi++)
#pragma unroll
                for (int nj = 0; nj < 8; nj++)
                    mma16816(acc[mi][nj], af[mi],
                             bf[nj >> 1][(nj & 1) * 2], bf[nj >> 1][(nj & 1) * 2 + 1]);
        }
        // no trailing barrier: next iteration's syncthreads protects stage reuse
    }

    epilogue(reinterpret_cast<const float*>(smem + BBIAS),
             reinterpret_cast<float*>(smem + BROW),
             acc, wm, wn, lane, tid, region, row0, count, listp);
}

// ---------------- kernel 3: finalize NLL ----------------
__global__ void finalize_kernel(float* __restrict__ out) {
    int t = blockIdx.x * blockDim.x + threadIdx.x;
    if (t >= NTOK) return;
    int r = g_cid[t];
    float ch = __expf(g_clogit[t][0]) + __expf(g_clogit[t][1]) + __expf(g_clogit[t][2]);
    float lse_head = __logf(g_S[0][t] + ch);
    float nll;
    if (r == 0) {
        nll = lse_head - g_tlogit[t];
    } else {
        float lse_tail = __logf(g_S[r][t]);
        // reference: head_logprob[:, -i] for region i -> cluster column (3 - i)
        nll = lse_head + lse_tail - g_clogit[t][3 - r] - g_tlogit[t];
    }
    out[t] = nll;
}

// ---------------- launcher ----------------
extern "C" void kernel_launch(void* const* d_in, const int* in_sizes, int n_in,
                              void* d_out, int out_size) {
    const float* hidden = (const float*)d_in[0];
    const int*   target = (const int*)d_in[1];
    const float* weight = (const float*)d_in[2];
    const float* bias   = (const float*)d_in[3];
    const float* cw     = (const float*)d_in[4];
    const float* cb     = (const float*)d_in[5];
    float* out = (float*)d_out;

    cudaFuncSetAttribute(gemm_sumexp,
                         cudaFuncAttributeMaxDynamicSharedMemorySize, BSMEM);
    cudaFuncSetAttribute(conv_gemm_sumexp,
                         cudaFuncAttributeMaxDynamicSharedMemorySize, CSMEM);

    zero_kernel<<<1, 256>>>();
    prep_kernel<<<128, 256>>>(hidden, target, weight, bias, cw, cb);

    // bf16 hidden (tiny)
    __nv_bfloat16* d_hbf = nullptr; cudaGetSymbolAddress((void**)&d_hbf, g_hbf);
    const size_t h8 = (size_t)NTOK * DIN / 8;
    convert_kernel<<<(unsigned)((h8 + 255) / 256), 256>>>(hidden, d_hbf, h8);

    // M-tile 0 GEMM fused with weight convert (writes g_wbf), then M-tiles 1..7
    conv_gemm_sumexp<<<dim3(1, NT_TOTAL), GT, CSMEM>>>(weight, bias);
    gemm_sumexp<<<dim3(7, NT_TOTAL), GT, BSMEM>>>(bias);

    finalize_kernel<<<4, 256>>>(out);
}